// round 4
// baseline (speedup 1.0000x reference)
#include <cuda_runtime.h>
#include <math.h>

#define NUM_LAYERS 6
#define CDIM 768
#define NHEADS 12
#define DHEAD 64
#define LATD 256
#define NTOK 65
#define BATCH 512
#define ROWS (BATCH*NTOK)          // 33280
#define C3 (3*CDIM)                // 2304
#define C4 (4*CDIM)                // 3072
#define BHD (BATCH*NHEADS)         // 6144
#define BIASN (NTOK*NTOK)          // 4225

// ---------------- scratch (static device allocations; no cudaMalloc) ----------------
__device__ float g_h   [(size_t)ROWS*CDIM];   // LN1 / LN2 output
__device__ float g_qkv [(size_t)ROWS*C3];     // qkv (q,k normalized in place)
__device__ float g_o   [(size_t)ROWS*CDIM];   // attention output, (B,N,H*DH)
__device__ float g_gated[(size_t)ROWS*C4];    // gate * silu(value)
__device__ float g_bias[(size_t)BHD*BIASN];   // attention bias (B*H, 65*65)
__device__ float g_sg1 [512*512];
__device__ float g_sg2 [512*3072];

// ---------------- helpers ----------------
__device__ __forceinline__ unsigned f2tf32(float x){
    unsigned r; asm("cvt.rna.tf32.f32 %0, %1;" : "=r"(r) : "f"(x)); return r;
}
__device__ __forceinline__ void mma_tf32(float c[4],
        unsigned a0, unsigned a1, unsigned a2, unsigned a3,
        unsigned b0, unsigned b1){
    asm volatile(
      "mma.sync.aligned.m16n8k8.row.col.f32.tf32.tf32.f32 "
      "{%0,%1,%2,%3}, {%4,%5,%6,%7}, {%8,%9}, {%0,%1,%2,%3};\n"
      : "+f"(c[0]), "+f"(c[1]), "+f"(c[2]), "+f"(c[3])
      : "r"(a0), "r"(a1), "r"(a2), "r"(a3), "r"(b0), "r"(b1));
}

// ---------------- tf32 GEMM: C[M,N] = A[M,K] @ B[K,N]  (EPI=0 store, EPI=1 += ) -------
// Requires: M % 128 == 0, K % 16 == 0, lda/acol 4-aligned. N arbitrary (guarded).
template<int EPI>
__global__ void __launch_bounds__(256)
gemm_tf32_kernel(const float* __restrict__ A, const float* __restrict__ B,
                 float* __restrict__ C, int M, int N, int K,
                 int lda, int ldb, int ldc)
{
    constexpr int BM=128, BN=128, BK=16;
    constexpr int AST=BK+4;    // 20: (20*g+q)%32 distinct for g<8,q<4
    constexpr int BST=BN+8;    // 136: (8*q+g)%32 distinct
    __shared__ float As[2][BM*AST];
    __shared__ float Bs[2][BK*BST];

    const int tid  = threadIdx.x;
    const int wid  = tid >> 5, lane = tid & 31;
    const int wm   = wid >> 2, wn   = wid & 3;      // 2 x 4 warps, warp tile 64x32
    const int g    = lane >> 2, q   = lane & 3;
    const long long bm = (long long)blockIdx.y * BM;
    const int bn   = blockIdx.x * BN;

    const int arow = tid >> 2, acol = (tid & 3) * 4;   // A: 2 x float4 per thread
    const int brow = tid >> 5, bcol = (tid & 31) * 4;  // B: 8 scalars per thread

    float acc[4][4][4];
    #pragma unroll
    for (int i=0;i<4;i++)
      #pragma unroll
      for (int j=0;j<4;j++)
        #pragma unroll
        for (int r=0;r<4;r++) acc[i][j][r]=0.f;

    float a_ld[8], b_ld[8];

    auto LOAD = [&](int kt){
        const float* Ap = A + (bm + arow)*lda + kt*BK + acol;
        float4 v0 = *(const float4*)Ap;
        float4 v1 = *(const float4*)(Ap + 64LL*lda);
        a_ld[0]=v0.x; a_ld[1]=v0.y; a_ld[2]=v0.z; a_ld[3]=v0.w;
        a_ld[4]=v1.x; a_ld[5]=v1.y; a_ld[6]=v1.z; a_ld[7]=v1.w;
        #pragma unroll
        for (int i=0;i<4;i++){
            int col = bn + bcol + i;
            bool ok = (col < N);
            b_ld[i]   = ok ? B[(long long)(kt*BK + brow    )*ldb + col] : 0.f;
            b_ld[4+i] = ok ? B[(long long)(kt*BK + brow + 8)*ldb + col] : 0.f;
        }
    };
    auto STORE_SM = [&](int s){
        #pragma unroll
        for (int i=0;i<4;i++){
            As[s][(arow   )*AST + acol + i] = __uint_as_float(f2tf32(a_ld[i]));
            As[s][(arow+64)*AST + acol + i] = __uint_as_float(f2tf32(a_ld[4+i]));
            Bs[s][(brow   )*BST + bcol + i] = __uint_as_float(f2tf32(b_ld[i]));
            Bs[s][(brow+8 )*BST + bcol + i] = __uint_as_float(f2tf32(b_ld[4+i]));
        }
    };
    auto COMPUTE = [&](int s){
        #pragma unroll
        for (int ks=0; ks<2; ks++){
            const int kk = ks*8;
            unsigned af[4][4], bf[4][2];
            #pragma unroll
            for (int i=0;i<4;i++){
                int r0 = wm*64 + i*16 + g;
                af[i][0]=__float_as_uint(As[s][(r0  )*AST + kk + q    ]);
                af[i][1]=__float_as_uint(As[s][(r0+8)*AST + kk + q    ]);
                af[i][2]=__float_as_uint(As[s][(r0  )*AST + kk + q + 4]);
                af[i][3]=__float_as_uint(As[s][(r0+8)*AST + kk + q + 4]);
            }
            #pragma unroll
            for (int j=0;j<4;j++){
                int c0 = wn*32 + j*8 + g;
                bf[j][0]=__float_as_uint(Bs[s][(kk + q    )*BST + c0]);
                bf[j][1]=__float_as_uint(Bs[s][(kk + q + 4)*BST + c0]);
            }
            #pragma unroll
            for (int i=0;i<4;i++)
              #pragma unroll
              for (int j=0;j<4;j++)
                mma_tf32(acc[i][j], af[i][0],af[i][1],af[i][2],af[i][3],
                         bf[j][0], bf[j][1]);
        }
    };

    const int ktiles = K / BK;
    LOAD(0); STORE_SM(0); __syncthreads();
    for (int t=0; t<ktiles; t++){
        int cur = t & 1;
        if (t+1 < ktiles) LOAD(t+1);
        COMPUTE(cur);
        if (t+1 < ktiles) STORE_SM(cur ^ 1);
        __syncthreads();
    }

    #pragma unroll
    for (int i=0;i<4;i++){
        long long row = bm + wm*64 + i*16 + g;
        float* Cp0 = C + row*ldc;
        float* Cp1 = C + (row+8)*ldc;
        #pragma unroll
        for (int j=0;j<4;j++){
            int col = bn + wn*32 + j*8 + q*2;
            if (col < N){
                if (EPI==0){ Cp0[col]=acc[i][j][0]; Cp1[col]=acc[i][j][2]; }
                else       { Cp0[col]+=acc[i][j][0]; Cp1[col]+=acc[i][j][2]; }
            }
            if (col+1 < N){
                if (EPI==0){ Cp0[col+1]=acc[i][j][1]; Cp1[col+1]=acc[i][j][3]; }
                else       { Cp0[col+1]+=acc[i][j][1]; Cp1[col+1]+=acc[i][j][3]; }
            }
        }
    }
}

// -------- dual GEMM: C = (A@B1) * silu(A@B2), BN=64, N%64==0, ldb%4==0 --------
__global__ void __launch_bounds__(256)
gemm_dual_tf32_kernel(const float* __restrict__ A, const float* __restrict__ B1,
                      const float* __restrict__ B2, float* __restrict__ C,
                      int M, int N, int K, int lda, int ldb, int ldc)
{
    constexpr int BM=128, BN=64, BK=16;
    constexpr int AST=BK+4;   // 20
    constexpr int BST=BN+8;   // 72
    __shared__ float As [2][BM*AST];
    __shared__ float B1s[2][BK*BST];
    __shared__ float B2s[2][BK*BST];

    const int tid  = threadIdx.x;
    const int wid  = tid >> 5, lane = tid & 31;
    const int wm   = wid >> 2, wn   = wid & 3;      // 2 x 4 warps, warp tile 64x16
    const int g    = lane >> 2, q   = lane & 3;
    const long long bm = (long long)blockIdx.y * BM;
    const int bn   = blockIdx.x * BN;

    const int arow = tid >> 2, acol = (tid & 3) * 4;
    const int brow = tid >> 4, bcol = (tid & 15) * 4;  // 16x64, one float4 per matrix

    float accg[4][2][4], accv[4][2][4];
    #pragma unroll
    for (int i=0;i<4;i++)
      #pragma unroll
      for (int j=0;j<2;j++)
        #pragma unroll
        for (int r=0;r<4;r++){ accg[i][j][r]=0.f; accv[i][j][r]=0.f; }

    float a_ld[8]; float4 b1_ld, b2_ld;

    auto LOAD = [&](int kt){
        const float* Ap = A + (bm + arow)*lda + kt*BK + acol;
        float4 v0 = *(const float4*)Ap;
        float4 v1 = *(const float4*)(Ap + 64LL*lda);
        a_ld[0]=v0.x; a_ld[1]=v0.y; a_ld[2]=v0.z; a_ld[3]=v0.w;
        a_ld[4]=v1.x; a_ld[5]=v1.y; a_ld[6]=v1.z; a_ld[7]=v1.w;
        long long off = (long long)(kt*BK + brow)*ldb + bn + bcol;
        b1_ld = *(const float4*)(B1 + off);
        b2_ld = *(const float4*)(B2 + off);
    };
    auto STORE_SM = [&](int s){
        #pragma unroll
        for (int i=0;i<4;i++){
            As[s][(arow   )*AST + acol + i] = __uint_as_float(f2tf32(a_ld[i]));
            As[s][(arow+64)*AST + acol + i] = __uint_as_float(f2tf32(a_ld[4+i]));
        }
        float b1v[4] = {b1_ld.x,b1_ld.y,b1_ld.z,b1_ld.w};
        float b2v[4] = {b2_ld.x,b2_ld.y,b2_ld.z,b2_ld.w};
        #pragma unroll
        for (int i=0;i<4;i++){
            B1s[s][brow*BST + bcol + i] = __uint_as_float(f2tf32(b1v[i]));
            B2s[s][brow*BST + bcol + i] = __uint_as_float(f2tf32(b2v[i]));
        }
    };
    auto COMPUTE = [&](int s){
        #pragma unroll
        for (int ks=0; ks<2; ks++){
            const int kk = ks*8;
            unsigned af[4][4], bf1[2][2], bf2[2][2];
            #pragma unroll
            for (int i=0;i<4;i++){
                int r0 = wm*64 + i*16 + g;
                af[i][0]=__float_as_uint(As[s][(r0  )*AST + kk + q    ]);
                af[i][1]=__float_as_uint(As[s][(r0+8)*AST + kk + q    ]);
                af[i][2]=__float_as_uint(As[s][(r0  )*AST + kk + q + 4]);
                af[i][3]=__float_as_uint(As[s][(r0+8)*AST + kk + q + 4]);
            }
            #pragma unroll
            for (int j=0;j<2;j++){
                int c0 = wn*16 + j*8 + g;
                bf1[j][0]=__float_as_uint(B1s[s][(kk + q    )*BST + c0]);
                bf1[j][1]=__float_as_uint(B1s[s][(kk + q + 4)*BST + c0]);
                bf2[j][0]=__float_as_uint(B2s[s][(kk + q    )*BST + c0]);
                bf2[j][1]=__float_as_uint(B2s[s][(kk + q + 4)*BST + c0]);
            }
            #pragma unroll
            for (int i=0;i<4;i++)
              #pragma unroll
              for (int j=0;j<2;j++){
                mma_tf32(accg[i][j], af[i][0],af[i][1],af[i][2],af[i][3], bf1[j][0], bf1[j][1]);
                mma_tf32(accv[i][j], af[i][0],af[i][1],af[i][2],af[i][3], bf2[j][0], bf2[j][1]);
              }
        }
    };

    const int ktiles = K / BK;
    LOAD(0); STORE_SM(0); __syncthreads();
    for (int t=0; t<ktiles; t++){
        int cur = t & 1;
        if (t+1 < ktiles) LOAD(t+1);
        COMPUTE(cur);
        if (t+1 < ktiles) STORE_SM(cur ^ 1);
        __syncthreads();
    }

    #pragma unroll
    for (int i=0;i<4;i++){
        long long row = bm + wm*64 + i*16 + g;
        float* Cp0 = C + row*ldc;
        float* Cp1 = C + (row+8)*ldc;
        #pragma unroll
        for (int j=0;j<2;j++){
            int col = bn + wn*16 + j*8 + q*2;
            #pragma unroll
            for (int r=0;r<4;r++){
                float gg = accg[i][j][r];
                float vv = accv[i][j][r];
                float out = gg * (vv / (1.f + expf(-vv)));
                float* Cp = (r < 2) ? Cp0 : Cp1;
                Cp[col + (r & 1)] = out;
            }
        }
    }
}

// ---------------- LayerNorm (one row per block, 256 threads) ----------------
__global__ void ln_kernel(const float* __restrict__ in, float* __restrict__ out,
                          const float* __restrict__ gamma, const float* __restrict__ beta,
                          int W, int dosilu)
{
    long long row = blockIdx.x;
    const float* x = in + row*(long long)W;
    float* y = out + row*(long long)W;
    float s=0.f, s2=0.f;
    for (int i=threadIdx.x; i<W; i+=blockDim.x){ float v=x[i]; s+=v; s2+=v*v; }
    __shared__ float rs[32], rs2[32];
    int lane = threadIdx.x & 31, wid = threadIdx.x >> 5;
    #pragma unroll
    for (int o=16;o;o>>=1){ s += __shfl_xor_sync(0xffffffffu,s,o); s2 += __shfl_xor_sync(0xffffffffu,s2,o); }
    if (lane==0){ rs[wid]=s; rs2[wid]=s2; }
    __syncthreads();
    if (wid==0){
        float a  = (lane<8)? rs[lane]  : 0.f;
        float a2 = (lane<8)? rs2[lane] : 0.f;
        #pragma unroll
        for (int o=4;o;o>>=1){ a += __shfl_xor_sync(0xffffffffu,a,o); a2 += __shfl_xor_sync(0xffffffffu,a2,o); }
        if (lane==0){ rs[0]=a; rs2[0]=a2; }
    }
    __syncthreads();
    float mean = rs[0]/(float)W;
    float var  = rs2[0]/(float)W - mean*mean;
    float rstd = rsqrtf(var + 1e-5f);
    for (int i=threadIdx.x; i<W; i+=blockDim.x){
        float v = (x[i]-mean)*rstd*gamma[i] + beta[i];
        if (dosilu) v = v / (1.f + expf(-v));
        y[i] = v;
    }
}

// ---------------- QK LayerNorm over DH=64 (one warp per (row, q/k, head)) -----------
__global__ void qknorm_kernel(float* __restrict__ qkv,
                              const float* __restrict__ qg, const float* __restrict__ qb,
                              const float* __restrict__ kg, const float* __restrict__ kb)
{
    int w = (blockIdx.x*blockDim.x + threadIdx.x) >> 5;
    int lane = threadIdx.x & 31;
    if (w >= ROWS*24) return;
    int r = w / 24, rem = w % 24, t = rem / 12, h = rem % 12;
    float* p = qkv + (long long)r*C3 + t*CDIM + h*DHEAD;
    float v0 = p[lane], v1 = p[lane+32];
    float s = v0 + v1;
    #pragma unroll
    for (int o=16;o;o>>=1) s += __shfl_xor_sync(0xffffffffu,s,o);
    float mean = s * (1.f/64.f);
    float d0 = v0-mean, d1 = v1-mean;
    float s2 = d0*d0 + d1*d1;
    #pragma unroll
    for (int o=16;o;o>>=1) s2 += __shfl_xor_sync(0xffffffffu,s2,o);
    float rstd = rsqrtf(s2*(1.f/64.f) + 1e-5f);
    const float* gg = t ? kg : qg;
    const float* bb = t ? kb : qb;
    float scale = t ? 1.f : 0.125f;   // DH^-0.5 applied to q
    p[lane]    = (d0*rstd*gg[lane]    + bb[lane]   ) * scale;
    p[lane+32] = (d1*rstd*gg[lane+32] + bb[lane+32]) * scale;
}

// ---------------- fused attention per (b,h): S=qk^T+bias, softmax, O=S@v ------------
__global__ void __launch_bounds__(256)
attn_kernel(const float* __restrict__ qkv, const float* __restrict__ bias,
            float* __restrict__ o)
{
    int bh = blockIdx.x;
    int b  = bh / NHEADS, hh = bh % NHEADS;
    extern __shared__ float sm[];
    float* qs = sm;                     // 65*64
    float* kt = qs + NTOK*DHEAD;        // 64*65 (transposed: kt[d*65+j])
    float* vs = kt + DHEAD*NTOK;        // 65*64
    float* S  = vs + NTOK*DHEAD;        // 65*65
    int tid = threadIdx.x;

    for (int idx=tid; idx<NTOK*DHEAD; idx+=256){
        int n = idx >> 6, d = idx & 63;
        const float* base = qkv + (long long)(b*NTOK+n)*C3 + hh*DHEAD + d;
        qs[idx]        = base[0];
        kt[d*NTOK + n] = base[CDIM];
        vs[idx]        = base[2*CDIM];
    }
    __syncthreads();

    const float* bb = bias + (long long)bh*BIASN;
    for (int idx=tid; idx<NTOK*NTOK; idx+=256){
        int i = idx / NTOK, j = idx - i*NTOK;
        float acc = bb[idx];
        const float* qr = qs + i*DHEAD;
        #pragma unroll 16
        for (int d=0; d<DHEAD; d++) acc += qr[d]*kt[d*NTOK + j];
        S[idx] = acc;
    }
    __syncthreads();

    int wid = tid >> 5, lane = tid & 31;
    for (int i=wid; i<NTOK; i+=8){
        float* Sr = S + i*NTOK;
        float m = -1e30f;
        for (int j=lane; j<NTOK; j+=32) m = fmaxf(m, Sr[j]);
        #pragma unroll
        for (int off=16;off;off>>=1) m = fmaxf(m, __shfl_xor_sync(0xffffffffu,m,off));
        float sum = 0.f;
        for (int j=lane; j<NTOK; j+=32){ float e = expf(Sr[j]-m); Sr[j]=e; sum+=e; }
        #pragma unroll
        for (int off=16;off;off>>=1) sum += __shfl_xor_sync(0xffffffffu,sum,off);
        float inv = 1.f/sum;
        for (int j=lane; j<NTOK; j+=32) Sr[j] *= inv;
    }
    __syncthreads();

    for (int idx=tid; idx<NTOK*DHEAD; idx+=256){
        int i = idx >> 6, d = idx & 63;
        float acc = 0.f;
        const float* Sr = S + i*NTOK;
        #pragma unroll 13
        for (int j=0; j<NTOK; j++) acc += Sr[j]*vs[j*DHEAD + d];
        o[(long long)(b*NTOK+i)*CDIM + hh*DHEAD + d] = acc;
    }
}

// ---------------- host ----------------
extern "C" void kernel_launch(void* const* d_in, const int* in_sizes, int n_in,
                              void* d_out, int out_size)
{
    (void)in_sizes; (void)n_in; (void)out_size;
    const float* ln1_g  = (const float*)d_in[1];
    const float* ln1_b  = (const float*)d_in[2];
    const float* qkv_w  = (const float*)d_in[3];
    const float* proj_w = (const float*)d_in[4];
    const float* qn_g   = (const float*)d_in[5];
    const float* qn_b   = (const float*)d_in[6];
    const float* kn_g   = (const float*)d_in[7];
    const float* kn_b   = (const float*)d_in[8];
    const float* sg_w1  = (const float*)d_in[9];
    const float* sg1g   = (const float*)d_in[10];
    const float* sg1b   = (const float*)d_in[11];
    const float* sg_w2  = (const float*)d_in[12];
    const float* sg2g   = (const float*)d_in[13];
    const float* sg2b   = (const float*)d_in[14];
    const float* bw     = (const float*)d_in[15];
    const float* ln2_g  = (const float*)d_in[16];
    const float* ln2_b  = (const float*)d_in[17];
    const float* gate_w = (const float*)d_in[18];
    const float* value_w= (const float*)d_in[19];
    const float* out_w  = (const float*)d_in[20];

    float* X = (float*)d_out;

    void *ph, *pqkv, *po, *pgated, *pbias, *psg1, *psg2;
    cudaGetSymbolAddress(&ph,    g_h);
    cudaGetSymbolAddress(&pqkv,  g_qkv);
    cudaGetSymbolAddress(&po,    g_o);
    cudaGetSymbolAddress(&pgated,g_gated);
    cudaGetSymbolAddress(&pbias, g_bias);
    cudaGetSymbolAddress(&psg1,  g_sg1);
    cudaGetSymbolAddress(&psg2,  g_sg2);
    float* h     = (float*)ph;
    float* qkv   = (float*)pqkv;
    float* o     = (float*)po;
    float* gated = (float*)pgated;
    float* bias  = (float*)pbias;
    float* sg1   = (float*)psg1;
    float* sg2   = (float*)psg2;

    const int attn_smem = (NTOK*DHEAD + DHEAD*NTOK + NTOK*DHEAD + NTOK*NTOK) * 4;
    cudaFuncSetAttribute(attn_kernel, cudaFuncAttributeMaxDynamicSharedMemorySize, attn_smem);

    // x -> running residual stream in d_out
    cudaMemcpyAsync(X, d_in[0], sizeof(float)*(size_t)ROWS*CDIM, cudaMemcpyDeviceToDevice);

    for (int l=0; l<NUM_LAYERS; l++){
        // h = LN1(x)
        ln_kernel<<<ROWS,256>>>(X, h, ln1_g + (size_t)l*CDIM, ln1_b + (size_t)l*CDIM, CDIM, 0);
        // qkv = h @ qkv_w
        gemm_tf32_kernel<0><<<dim3(C3/128, ROWS/128), 256>>>(
            h, qkv_w + (size_t)l*CDIM*C3, qkv, ROWS, C3, CDIM, CDIM, C3, C3);
        // q,k norm (+q scale) in place
        qknorm_kernel<<<(ROWS*24)/8, 256>>>(qkv,
            qn_g + (size_t)l*DHEAD, qn_b + (size_t)l*DHEAD,
            kn_g + (size_t)l*DHEAD, kn_b + (size_t)l*DHEAD);
        // structure-gate bias MLP (cls rows of h, lda = N*C)
        gemm_tf32_kernel<0><<<dim3(4,4), 256>>>(
            h, sg_w1 + (size_t)l*CDIM*512, sg1, 512, 512, CDIM, NTOK*CDIM, 512, 512);
        ln_kernel<<<512,256>>>(sg1, sg1, sg1g + (size_t)l*512, sg1b + (size_t)l*512, 512, 1);
        gemm_tf32_kernel<0><<<dim3(24,4), 256>>>(
            sg1, sg_w2 + (size_t)l*512*3072, sg2, 512, 3072, 512, 512, 3072, 3072);
        ln_kernel<<<512,256>>>(sg2, sg2, sg2g + (size_t)l*3072, sg2b + (size_t)l*3072, 3072, 0);
        // bias = lat2(B*H,256) @ bw(256,4225)
        gemm_tf32_kernel<0><<<dim3((BIASN+127)/128, BHD/128), 256>>>(
            sg2, bw + (size_t)l*LATD*BIASN, bias, BHD, BIASN, LATD, LATD, BIASN, BIASN);
        // fused attention
        attn_kernel<<<BHD, 256, attn_smem>>>(qkv, bias, o);
        // x += o @ proj_w
        gemm_tf32_kernel<1><<<dim3(CDIM/128, ROWS/128), 256>>>(
            o, proj_w + (size_t)l*CDIM*CDIM, X, ROWS, CDIM, CDIM, CDIM, CDIM, CDIM);
        // h2 = LN2(x)
        ln_kernel<<<ROWS,256>>>(X, h, ln2_g + (size_t)l*CDIM, ln2_b + (size_t)l*CDIM, CDIM, 0);
        // gated = (h2@gate_w) * silu(h2@value_w)
        gemm_dual_tf32_kernel<<<dim3(C4/64, ROWS/128), 256>>>(
            h, gate_w + (size_t)l*CDIM*C4, value_w + (size_t)l*CDIM*C4, gated,
            ROWS, C4, CDIM, CDIM, C4, C4);
        // x += gated @ out_w
        gemm_tf32_kernel<1><<<dim3(CDIM/128, ROWS/128), 256>>>(
            gated, out_w + (size_t)l*C4*CDIM, X, ROWS, CDIM, C4, C4, CDIM, CDIM);
    }
}

// round 8
// speedup vs baseline: 2.3985x; 2.3985x over previous
#include <cuda_runtime.h>
#include <cuda_fp16.h>
#include <math.h>
#include <stdint.h>

#define NUM_LAYERS 6
#define CDIM 768
#define NHEADS 12
#define DHEAD 64
#define LATD 256
#define NTOK 65
#define BATCH 512
#define ROWS (BATCH*NTOK)          // 33280
#define C3 (3*CDIM)                // 2304
#define C4 (4*CDIM)                // 3072
#define BHD (BATCH*NHEADS)         // 6144
#define BIASN (NTOK*NTOK)          // 4225
#define BIASNP 4352                // padded to %128

// ---------------- scratch (static device allocations; no cudaMalloc) ----------------
__device__ __align__(256) __half g_h    [(size_t)ROWS*CDIM];   // LN1/LN2 out (fp16)
__device__ __align__(256) float  g_qkv  [(size_t)ROWS*C3];     // qkv fp32
__device__ __align__(256) __half g_o    [(size_t)ROWS*CDIM];   // attn out (fp16)
__device__ __align__(256) __half g_gated[(size_t)ROWS*C4];     // gate*silu(value) fp16
__device__ __align__(256) float  g_bias [(size_t)BHD*BIASN];
__device__ __align__(256) float  g_sg1  [512*512];
__device__ __align__(256) __half g_sg1h [512*512];
__device__ __align__(256) float  g_sg2  [512*3072];
__device__ __align__(256) __half g_sg2h [512*3072];
// transposed (K-major, [N][K]) fp16 weights, reused per layer
__device__ __align__(256) __half g_tqkv [C3*CDIM];
__device__ __align__(256) __half g_tproj[CDIM*CDIM];
__device__ __align__(256) __half g_tgate[C4*CDIM];
__device__ __align__(256) __half g_tval [C4*CDIM];
__device__ __align__(256) __half g_tout [CDIM*C4];
__device__ __align__(256) __half g_tsg1 [512*CDIM];
__device__ __align__(256) __half g_tsg2 [3072*512];
__device__ __align__(256) __half g_tbw  [(size_t)BIASNP*LATD];

// ---------------- PTX helpers ----------------
__device__ __forceinline__ uint32_t smem_u32(const void* p){
    uint32_t a;
    asm("{ .reg .u64 t; cvta.to.shared.u64 t, %1; cvt.u32.u64 %0, t; }" : "=r"(a) : "l"(p));
    return a;
}
__device__ __forceinline__ void cpa16(uint32_t s, const void* g){
    asm volatile("cp.async.cg.shared.global [%0], [%1], 16;" :: "r"(s), "l"(g));
}
#define CP_COMMIT() asm volatile("cp.async.commit_group;")
#define CP_WAIT1()  asm volatile("cp.async.wait_group 1;")
__device__ __forceinline__ void ldsm4(uint32_t* r, uint32_t addr){
    asm volatile("ldmatrix.sync.aligned.m8n8.x4.shared.b16 {%0,%1,%2,%3}, [%4];"
        : "=r"(r[0]),"=r"(r[1]),"=r"(r[2]),"=r"(r[3]) : "r"(addr));
}
__device__ __forceinline__ void mma16816(float* c, const uint32_t* a, uint32_t b0, uint32_t b1){
    asm volatile(
      "mma.sync.aligned.m16n8k16.row.col.f32.f16.f16.f32 "
      "{%0,%1,%2,%3},{%4,%5,%6,%7},{%8,%9},{%0,%1,%2,%3};"
      : "+f"(c[0]),"+f"(c[1]),"+f"(c[2]),"+f"(c[3])
      : "r"(a[0]),"r"(a[1]),"r"(a[2]),"r"(a[3]),"r"(b0),"r"(b1));
}
__device__ __forceinline__ float silu_f(float v){ return v/(1.f+expf(-v)); }

// smem geometry: rows of 32 halves padded to 40 halves (80B). conflict-free for
// both cp.async 16B stores and ldmatrix (row word-offsets span all 32 banks).
#define SROW   80
#define ASTG   (128*SROW)     // 10240 B per A stage
#define NSTAGE 3

// =====================================================================================
// fp16 GEMM: C[M,N](fp32) = A[M,K](fp16 row-major) @ Bt[N][K](fp16 K-major)^T
// Tile 128x128x32, 3-stage cp.async pipeline, ldmatrix + mma.m16n8k16.
// EPI: 0 = store, 1 = residual add. NGUARD: guard C cols < N.
// Requires M%128==0, Bt padded to N%128 rows, K%32==0, lda/K %8==0.
// =====================================================================================
template<int EPI, bool NGUARD>
__global__ void __launch_bounds__(256,2)
gemm_h(const __half* __restrict__ A, const __half* __restrict__ Bt,
       float* __restrict__ C, int M, int N, int K, int lda, int ldc)
{
    extern __shared__ __align__(128) char dyn[];
    const uint32_t sA = smem_u32(dyn);
    const uint32_t sB = sA + NSTAGE*ASTG;

    const int tid = threadIdx.x, wid = tid>>5, lane = tid&31;
    const int wm = wid>>2, wn = wid&3;           // 2x4 warps, warp tile 64x32
    const size_t bm = (size_t)blockIdx.y*128;
    const size_t bn = (size_t)blockIdx.x*128;
    const int KT = K/32;

    float acc[4][4][4];
    #pragma unroll
    for (int i=0;i<4;i++) for (int j=0;j<4;j++) for (int r=0;r<4;r++) acc[i][j][r]=0.f;

    auto LOADS = [&](int s, int t){
        const uint32_t sa = sA + s*ASTG, sb = sB + s*ASTG;
        #pragma unroll
        for (int u=0;u<2;u++){
            int c = tid + u*256;
            int row = c>>2, col8 = (c&3)*8;
            cpa16(sa + row*SROW + col8*2, A  + (bm+row)*(size_t)lda + (size_t)t*32 + col8);
            cpa16(sb + row*SROW + col8*2, Bt + (bn+row)*(size_t)K   + (size_t)t*32 + col8);
        }
    };
    auto COMPUTE = [&](int s){
        const uint32_t sa = sA + s*ASTG, sb = sB + s*ASTG;
        #pragma unroll
        for (int kc=0;kc<2;kc++){
            uint32_t af[4][4], bf[2][4];
            #pragma unroll
            for (int i=0;i<4;i++){
                int r = wm*64 + i*16 + (lane&7) + ((lane>>3)&1)*8;
                int k = kc*16 + (lane>>4)*8;
                ldsm4(af[i], sa + r*SROW + k*2);
            }
            #pragma unroll
            for (int jj=0;jj<2;jj++){
                int n = wn*32 + jj*16 + ((lane>>4)<<3) + (lane&7);
                int k = kc*16 + ((lane>>3)&1)*8;
                ldsm4(bf[jj], sb + n*SROW + k*2);
            }
            #pragma unroll
            for (int i=0;i<4;i++)
              #pragma unroll
              for (int jj=0;jj<2;jj++){
                mma16816(acc[i][jj*2  ], af[i], bf[jj][0], bf[jj][1]);
                mma16816(acc[i][jj*2+1], af[i], bf[jj][2], bf[jj][3]);
              }
        }
    };

    LOADS(0,0); CP_COMMIT();
    if (KT>1) LOADS(1,1);
    CP_COMMIT();
    for (int t=0;t<KT;t++){
        CP_WAIT1();
        __syncthreads();
        COMPUTE(t%NSTAGE);
        int nt = t+2;
        if (nt<KT) LOADS(nt%NSTAGE, nt);
        CP_COMMIT();
    }

    // epilogue
    const int r4 = lane>>2, c2 = (lane&3)*2;
    #pragma unroll
    for (int i=0;i<4;i++){
        size_t r0 = bm + wm*64 + i*16 + r4;
        float* Cp0 = C + r0*(size_t)ldc;
        float* Cp1 = Cp0 + 8*(size_t)ldc;
        #pragma unroll
        for (int j=0;j<4;j++){
            size_t col = bn + wn*32 + j*8 + c2;
            if (!NGUARD){
                float2* p0 = (float2*)(Cp0+col);
                float2* p1 = (float2*)(Cp1+col);
                float2 v0 = make_float2(acc[i][j][0], acc[i][j][1]);
                float2 v1 = make_float2(acc[i][j][2], acc[i][j][3]);
                if (EPI==1){ float2 o0=*p0, o1=*p1; v0.x+=o0.x; v0.y+=o0.y; v1.x+=o1.x; v1.y+=o1.y; }
                *p0 = v0; *p1 = v1;
            } else {
                if ((long long)col < N){
                    float v = acc[i][j][0]; if (EPI==1) v += Cp0[col]; Cp0[col]=v;
                    v = acc[i][j][2]; if (EPI==1) v += Cp1[col]; Cp1[col]=v;
                }
                if ((long long)col+1 < N){
                    float v = acc[i][j][1]; if (EPI==1) v += Cp0[col+1]; Cp0[col+1]=v;
                    v = acc[i][j][3]; if (EPI==1) v += Cp1[col+1]; Cp1[col+1]=v;
                }
            }
        }
    }
}

// =====================================================================================
// dual fp16 GEMM: C(fp16) = (A@G^T) * silu(A@V^T). Tile 128x64x32.
// =====================================================================================
__global__ void __launch_bounds__(256,2)
gemm_dual_h(const __half* __restrict__ A, const __half* __restrict__ Gt,
            const __half* __restrict__ Vt, __half* __restrict__ C,
            int M, int N, int K, int lda, int ldc)
{
    extern __shared__ __align__(128) char dyn[];
    const uint32_t sA = smem_u32(dyn);
    const uint32_t sG = sA + NSTAGE*ASTG;
    const uint32_t sV = sG + NSTAGE*(64*SROW);

    const int tid = threadIdx.x, wid = tid>>5, lane = tid&31;
    const int wm = wid>>2, wn = wid&3;           // warp tile 64x16
    const size_t bm = (size_t)blockIdx.y*128;
    const size_t bn = (size_t)blockIdx.x*64;
    const int KT = K/32;

    float ag[4][2][4], av[4][2][4];
    #pragma unroll
    for (int i=0;i<4;i++) for (int j=0;j<2;j++) for (int r=0;r<4;r++){ ag[i][j][r]=0.f; av[i][j][r]=0.f; }

    auto LOADS = [&](int s, int t){
        const uint32_t sa = sA + s*ASTG;
        const uint32_t sg = sG + s*(64*SROW);
        const uint32_t sv = sV + s*(64*SROW);
        #pragma unroll
        for (int u=0;u<2;u++){
            int c = tid + u*256;
            int row = c>>2, col8 = (c&3)*8;
            cpa16(sa + row*SROW + col8*2, A + (bm+row)*(size_t)lda + (size_t)t*32 + col8);
        }
        {
            int row = tid>>2, col8 = (tid&3)*8;
            cpa16(sg + row*SROW + col8*2, Gt + (bn+row)*(size_t)K + (size_t)t*32 + col8);
            cpa16(sv + row*SROW + col8*2, Vt + (bn+row)*(size_t)K + (size_t)t*32 + col8);
        }
    };
    auto COMPUTE = [&](int s){
        const uint32_t sa = sA + s*ASTG;
        const uint32_t sg = sG + s*(64*SROW);
        const uint32_t sv = sV + s*(64*SROW);
        #pragma unroll
        for (int kc=0;kc<2;kc++){
            uint32_t af[4][4], gf[4], vf[4];
            #pragma unroll
            for (int i=0;i<4;i++){
                int r = wm*64 + i*16 + (lane&7) + ((lane>>3)&1)*8;
                int k = kc*16 + (lane>>4)*8;
                ldsm4(af[i], sa + r*SROW + k*2);
            }
            {
                int n = wn*16 + ((lane>>4)<<3) + (lane&7);
                int k = kc*16 + ((lane>>3)&1)*8;
                ldsm4(gf, sg + n*SROW + k*2);
                ldsm4(vf, sv + n*SROW + k*2);
            }
            #pragma unroll
            for (int i=0;i<4;i++){
                mma16816(ag[i][0], af[i], gf[0], gf[1]);
                mma16816(ag[i][1], af[i], gf[2], gf[3]);
                mma16816(av[i][0], af[i], vf[0], vf[1]);
                mma16816(av[i][1], af[i], vf[2], vf[3]);
            }
        }
    };

    LOADS(0,0); CP_COMMIT();
    if (KT>1) LOADS(1,1);
    CP_COMMIT();
    for (int t=0;t<KT;t++){
        CP_WAIT1();
        __syncthreads();
        COMPUTE(t%NSTAGE);
        int nt = t+2;
        if (nt<KT) LOADS(nt%NSTAGE, nt);
        CP_COMMIT();
    }

    const int r4 = lane>>2, c2 = (lane&3)*2;
    #pragma unroll
    for (int i=0;i<4;i++){
        size_t r0 = bm + wm*64 + i*16 + r4;
        __half* Cp0 = C + r0*(size_t)ldc;
        __half* Cp1 = Cp0 + 8*(size_t)ldc;
        #pragma unroll
        for (int j=0;j<2;j++){
            size_t col = bn + wn*16 + j*8 + c2;
            __half2 v0 = __floats2half2_rn(ag[i][j][0]*silu_f(av[i][j][0]),
                                           ag[i][j][1]*silu_f(av[i][j][1]));
            __half2 v1 = __floats2half2_rn(ag[i][j][2]*silu_f(av[i][j][2]),
                                           ag[i][j][3]*silu_f(av[i][j][3]));
            *(__half2*)(Cp0+col) = v0;
            *(__half2*)(Cp1+col) = v1;
        }
    }
}

// ---------------- LayerNorm (fp32 in, fp16 out; optional silu) ----------------
__global__ void ln_h_kernel(const float* __restrict__ in, __half* __restrict__ out,
                            const float* __restrict__ gamma, const float* __restrict__ beta,
                            int W, int dosilu)
{
    size_t row = blockIdx.x;
    const float* x = in + row*(size_t)W;
    __half* y = out + row*(size_t)W;
    float s=0.f, s2=0.f;
    for (int i=threadIdx.x; i<W; i+=blockDim.x){ float v=x[i]; s+=v; s2+=v*v; }
    __shared__ float rs[32], rs2[32];
    int lane = threadIdx.x & 31, wid = threadIdx.x >> 5;
    #pragma unroll
    for (int o=16;o;o>>=1){ s += __shfl_xor_sync(0xffffffffu,s,o); s2 += __shfl_xor_sync(0xffffffffu,s2,o); }
    if (lane==0){ rs[wid]=s; rs2[wid]=s2; }
    __syncthreads();
    if (wid==0){
        float a  = (lane<8)? rs[lane]  : 0.f;
        float a2 = (lane<8)? rs2[lane] : 0.f;
        #pragma unroll
        for (int o=4;o;o>>=1){ a += __shfl_xor_sync(0xffffffffu,a,o); a2 += __shfl_xor_sync(0xffffffffu,a2,o); }
        if (lane==0){ rs[0]=a; rs2[0]=a2; }
    }
    __syncthreads();
    float mean = rs[0]/(float)W;
    float var  = rs2[0]/(float)W - mean*mean;
    float rstd = rsqrtf(var + 1e-5f);
    for (int i=threadIdx.x; i<W; i+=blockDim.x){
        float v = (x[i]-mean)*rstd*gamma[i] + beta[i];
        if (dosilu) v = silu_f(v);
        y[i] = __float2half(v);
    }
}

// ---------------- QK LayerNorm over DH=64 (one warp per (row, q/k, head)) -----------
__global__ void qknorm_kernel(float* __restrict__ qkv,
                              const float* __restrict__ qg, const float* __restrict__ qb,
                              const float* __restrict__ kg, const float* __restrict__ kb)
{
    int w = (blockIdx.x*blockDim.x + threadIdx.x) >> 5;
    int lane = threadIdx.x & 31;
    if (w >= ROWS*24) return;
    int r = w / 24, rem = w % 24, t = rem / 12, h = rem % 12;
    float* p = qkv + (size_t)r*C3 + t*CDIM + h*DHEAD;
    float v0 = p[lane], v1 = p[lane+32];
    float s = v0 + v1;
    #pragma unroll
    for (int o=16;o;o>>=1) s += __shfl_xor_sync(0xffffffffu,s,o);
    float mean = s * (1.f/64.f);
    float d0 = v0-mean, d1 = v1-mean;
    float s2 = d0*d0 + d1*d1;
    #pragma unroll
    for (int o=16;o;o>>=1) s2 += __shfl_xor_sync(0xffffffffu,s2,o);
    float rstd = rsqrtf(s2*(1.f/64.f) + 1e-5f);
    const float* gg = t ? kg : qg;
    const float* bb = t ? kb : qb;
    float scale = t ? 1.f : 0.125f;
    p[lane]    = (d0*rstd*gg[lane]    + bb[lane]   ) * scale;
    p[lane+32] = (d1*rstd*gg[lane+32] + bb[lane+32]) * scale;
}

// ---------------- fused attention per (b,h); writes fp16 o ------------
__global__ void __launch_bounds__(256)
attn_kernel(const float* __restrict__ qkv, const float* __restrict__ bias,
            __half* __restrict__ o)
{
    int bh = blockIdx.x;
    int b  = bh / NHEADS, hh = bh % NHEADS;
    extern __shared__ float sm[];
    float* qs = sm;
    float* kt = qs + NTOK*DHEAD;
    float* vs = kt + DHEAD*NTOK;
    float* S  = vs + NTOK*DHEAD;
    int tid = threadIdx.x;

    for (int idx=tid; idx<NTOK*DHEAD; idx+=256){
        int n = idx >> 6, d = idx & 63;
        const float* base = qkv + (size_t)(b*NTOK+n)*C3 + hh*DHEAD + d;
        qs[idx]        = base[0];
        kt[d*NTOK + n] = base[CDIM];
        vs[idx]        = base[2*CDIM];
    }
    __syncthreads();

    const float* bb = bias + (size_t)bh*BIASN;
    for (int idx=tid; idx<NTOK*NTOK; idx+=256){
        int i = idx / NTOK, j = idx - i*NTOK;
        float acc = bb[idx];
        const float* qr = qs + i*DHEAD;
        #pragma unroll 16
        for (int d=0; d<DHEAD; d++) acc += qr[d]*kt[d*NTOK + j];
        S[idx] = acc;
    }
    __syncthreads();

    int wid = tid >> 5, lane = tid & 31;
    for (int i=wid; i<NTOK; i+=8){
        float* Sr = S + i*NTOK;
        float m = -1e30f;
        for (int j=lane; j<NTOK; j+=32) m = fmaxf(m, Sr[j]);
        #pragma unroll
        for (int off=16;off;off>>=1) m = fmaxf(m, __shfl_xor_sync(0xffffffffu,m,off));
        float sum = 0.f;
        for (int j=lane; j<NTOK; j+=32){ float e = expf(Sr[j]-m); Sr[j]=e; sum+=e; }
        #pragma unroll
        for (int off=16;off;off>>=1) sum += __shfl_xor_sync(0xffffffffu,sum,off);
        float inv = 1.f/sum;
        for (int j=lane; j<NTOK; j+=32) Sr[j] *= inv;
    }
    __syncthreads();

    for (int idx=tid; idx<NTOK*DHEAD; idx+=256){
        int i = idx >> 6, d = idx & 63;
        float acc = 0.f;
        const float* Sr = S + i*NTOK;
        #pragma unroll 13
        for (int j=0; j<NTOK; j++) acc += Sr[j]*vs[j*DHEAD + d];
        o[(size_t)(b*NTOK+i)*CDIM + hh*DHEAD + d] = __float2half(acc);
    }
}

// ---------------- weight transpose: fp32 in[K][N] -> fp16 out[Npad][K] --------------
__global__ void transpose_pad_h(const float* __restrict__ in, __half* __restrict__ out,
                                int K, int N, int Npad)
{
    __shared__ float t[32][33];
    int kb = blockIdx.y*32, nb = blockIdx.x*32;
    #pragma unroll
    for (int i=0;i<4;i++){
        int k = kb + threadIdx.y + i*8, n = nb + threadIdx.x;
        t[threadIdx.y+i*8][threadIdx.x] = (k<K && n<N) ? in[(size_t)k*N + n] : 0.f;
    }
    __syncthreads();
    #pragma unroll
    for (int i=0;i<4;i++){
        int n = nb + threadIdx.y + i*8, k = kb + threadIdx.x;
        if (n<Npad && k<K) out[(size_t)n*K + k] = __float2half(t[threadIdx.x][threadIdx.y+i*8]);
    }
}

// ---------------- host ----------------
static inline void tlaunch(const float* in, __half* out, int K, int N, int Npad){
    transpose_pad_h<<<dim3((Npad+31)/32,(K+31)/32), dim3(32,8)>>>(in, out, K, N, Npad);
}

extern "C" void kernel_launch(void* const* d_in, const int* in_sizes, int n_in,
                              void* d_out, int out_size)
{
    (void)in_sizes; (void)n_in; (void)out_size;
    const float* ln1_g  = (const float*)d_in[1];
    const float* ln1_b  = (const float*)d_in[2];
    const float* qkv_w  = (const float*)d_in[3];
    const float* proj_w = (const float*)d_in[4];
    const float* qn_g   = (const float*)d_in[5];
    const float* qn_b   = (const float*)d_in[6];
    const float* kn_g   = (const float*)d_in[7];
    const float* kn_b   = (const float*)d_in[8];
    const float* sg_w1  = (const float*)d_in[9];
    const float* sg1g   = (const float*)d_in[10];
    const float* sg1b   = (const float*)d_in[11];
    const float* sg_w2  = (const float*)d_in[12];
    const float* sg2g   = (const float*)d_in[13];
    const float* sg2b   = (const float*)d_in[14];
    const float* bw     = (const float*)d_in[15];
    const float* ln2_g  = (const float*)d_in[16];
    const float* ln2_b  = (const float*)d_in[17];
    const float* gate_w = (const float*)d_in[18];
    const float* value_w= (const float*)d_in[19];
    const float* out_w  = (const float*)d_in[20];

    float* X = (float*)d_out;

    void *ph,*pqkv,*po,*pgated,*pbias,*psg1,*psg1h,*psg2,*psg2h;
    void *ptqkv,*ptproj,*ptgate,*ptval,*ptout,*ptsg1,*ptsg2,*ptbw;
    cudaGetSymbolAddress(&ph,g_h); cudaGetSymbolAddress(&pqkv,g_qkv);
    cudaGetSymbolAddress(&po,g_o); cudaGetSymbolAddress(&pgated,g_gated);
    cudaGetSymbolAddress(&pbias,g_bias);
    cudaGetSymbolAddress(&psg1,g_sg1); cudaGetSymbolAddress(&psg1h,g_sg1h);
    cudaGetSymbolAddress(&psg2,g_sg2); cudaGetSymbolAddress(&psg2h,g_sg2h);
    cudaGetSymbolAddress(&ptqkv,g_tqkv); cudaGetSymbolAddress(&ptproj,g_tproj);
    cudaGetSymbolAddress(&ptgate,g_tgate); cudaGetSymbolAddress(&ptval,g_tval);
    cudaGetSymbolAddress(&ptout,g_tout); cudaGetSymbolAddress(&ptsg1,g_tsg1);
    cudaGetSymbolAddress(&ptsg2,g_tsg2); cudaGetSymbolAddress(&ptbw,g_tbw);
    __half* h=(__half*)ph; float* qkv=(float*)pqkv; __half* o=(__half*)po;
    __half* gated=(__half*)pgated; float* bias=(float*)pbias;
    float* sg1=(float*)psg1; __half* sg1h=(__half*)psg1h;
    float* sg2=(float*)psg2; __half* sg2h=(__half*)psg2h;
    __half* tqkv=(__half*)ptqkv; __half* tproj=(__half*)ptproj; __half* tgate=(__half*)ptgate;
    __half* tval=(__half*)ptval; __half* tout=(__half*)ptout; __half* tsg1=(__half*)ptsg1;
    __half* tsg2=(__half*)ptsg2; __half* tbw=(__half*)ptbw;

    const int attn_smem = (NTOK*DHEAD + DHEAD*NTOK + NTOK*DHEAD + NTOK*NTOK) * 4;
    cudaFuncSetAttribute(attn_kernel, cudaFuncAttributeMaxDynamicSharedMemorySize, attn_smem);
    const int g_smem = 2*NSTAGE*ASTG;                 // 61440
    const int d_smem = NSTAGE*ASTG + 2*NSTAGE*64*SROW;// 30720+30720 = 61440
    cudaFuncSetAttribute(gemm_h<0,false>, cudaFuncAttributeMaxDynamicSharedMemorySize, g_smem);
    cudaFuncSetAttribute(gemm_h<1,false>, cudaFuncAttributeMaxDynamicSharedMemorySize, g_smem);
    cudaFuncSetAttribute(gemm_h<0,true>,  cudaFuncAttributeMaxDynamicSharedMemorySize, g_smem);
    cudaFuncSetAttribute(gemm_dual_h,     cudaFuncAttributeMaxDynamicSharedMemorySize, d_smem);

    cudaMemcpyAsync(X, d_in[0], sizeof(float)*(size_t)ROWS*CDIM, cudaMemcpyDeviceToDevice);

    for (int l=0; l<NUM_LAYERS; l++){
        // fp16 K-major weights for this layer
        tlaunch(qkv_w  + (size_t)l*CDIM*C3,   tqkv,  CDIM, C3,   C3);
        tlaunch(proj_w + (size_t)l*CDIM*CDIM, tproj, CDIM, CDIM, CDIM);
        tlaunch(gate_w + (size_t)l*CDIM*C4,   tgate, CDIM, C4,   C4);
        tlaunch(value_w+ (size_t)l*CDIM*C4,   tval,  CDIM, C4,   C4);
        tlaunch(out_w  + (size_t)l*C4*CDIM,   tout,  C4,   CDIM, CDIM);
        tlaunch(sg_w1  + (size_t)l*CDIM*512,  tsg1,  CDIM, 512,  512);
        tlaunch(sg_w2  + (size_t)l*512*3072,  tsg2,  512,  3072, 3072);
        tlaunch(bw     + (size_t)l*LATD*BIASN,tbw,   LATD, BIASN, BIASNP);

        // h = LN1(x)  (fp16 out)
        ln_h_kernel<<<ROWS,256>>>(X, h, ln1_g+(size_t)l*CDIM, ln1_b+(size_t)l*CDIM, CDIM, 0);
        // qkv = h @ qkv_w
        gemm_h<0,false><<<dim3(C3/128, ROWS/128), 256, g_smem>>>(
            h, tqkv, qkv, ROWS, C3, CDIM, CDIM, C3);
        // q,k norm (+ q scale) in place
        qknorm_kernel<<<(ROWS*24)/8, 256>>>(qkv,
            qn_g+(size_t)l*DHEAD, qn_b+(size_t)l*DHEAD,
            kn_g+(size_t)l*DHEAD, kn_b+(size_t)l*DHEAD);
        // structure-gate MLP (cls rows of h, lda = NTOK*CDIM)
        gemm_h<0,false><<<dim3(4,4), 256, g_smem>>>(
            h, tsg1, sg1, 512, 512, CDIM, NTOK*CDIM, 512);
        ln_h_kernel<<<512,256>>>(sg1, sg1h, sg1g+(size_t)l*512, sg1b+(size_t)l*512, 512, 1);
        gemm_h<0,false><<<dim3(24,4), 256, g_smem>>>(
            sg1h, tsg2, sg2, 512, 3072, 512, 512, 3072);
        ln_h_kernel<<<512,256>>>(sg2, sg2h, sg2g+(size_t)l*3072, sg2b+(size_t)l*3072, 3072, 0);
        // bias = lat2(B*H,256) @ bw(256,4225)
        gemm_h<0,true><<<dim3(BIASNP/128, BHD/128), 256, g_smem>>>(
            sg2h, tbw, bias, BHD, BIASN, LATD, LATD, BIASN);
        // fused attention (fp16 o)
        attn_kernel<<<BHD, 256, attn_smem>>>(qkv, bias, o);
        // x += o @ proj_w
        gemm_h<1,false><<<dim3(CDIM/128, ROWS/128), 256, g_smem>>>(
            o, tproj, X, ROWS, CDIM, CDIM, CDIM, CDIM);
        // h2 = LN2(x)
        ln_h_kernel<<<ROWS,256>>>(X, h, ln2_g+(size_t)l*CDIM, ln2_b+(size_t)l*CDIM, CDIM, 0);
        // gated = (h2@gate_w) * silu(h2@value_w)   (fp16 out)
        gemm_dual_h<<<dim3(C4/64, ROWS/128), 256, d_smem>>>(
            h, tgate, tval, gated, ROWS, C4, CDIM, CDIM, C4);
        // x += gated @ out_w
        gemm_h<1,false><<<dim3(CDIM/128, ROWS/128), 256, g_smem>>>(
            gated, tout, X, ROWS, CDIM, C4, C4, CDIM);
    }
}

// round 9
// speedup vs baseline: 2.8898x; 1.2048x over previous
#include <cuda_runtime.h>
#include <cuda_fp16.h>
#include <math.h>
#include <stdint.h>

#define NUM_LAYERS 6
#define CDIM 768
#define NHEADS 12
#define DHEAD 64
#define LATD 256
#define NTOK 65
#define BATCH 512
#define ROWS (BATCH*NTOK)          // 33280
#define C3 (3*CDIM)                // 2304
#define C4 (4*CDIM)                // 3072
#define BHD (BATCH*NHEADS)         // 6144
#define BIASN (NTOK*NTOK)          // 4225
#define BIASNP 4352                // padded to %128

// ---------------- scratch (static device allocations; no cudaMalloc) ----------------
__device__ __align__(256) __half g_h    [(size_t)ROWS*CDIM];   // LN1/LN2 out (fp16)
__device__ __align__(256) float  g_qkv  [(size_t)ROWS*C3];     // qkv fp32
__device__ __align__(256) __half g_o    [(size_t)ROWS*CDIM];   // attn out (fp16)
__device__ __align__(256) __half g_gated[(size_t)ROWS*C4];     // gate*silu(value) fp16
__device__ __align__(256) float  g_bias [(size_t)BHD*BIASN];
__device__ __align__(256) float  g_sg1  [512*512];
__device__ __align__(256) __half g_sg1h [512*512];
__device__ __align__(256) float  g_sg2  [512*3072];
__device__ __align__(256) __half g_sg2h [512*3072];
// transposed (K-major, [N][K]) fp16 weights, reused per layer
__device__ __align__(256) __half g_tqkv [C3*CDIM];
__device__ __align__(256) __half g_tproj[CDIM*CDIM];
__device__ __align__(256) __half g_tgate[C4*CDIM];
__device__ __align__(256) __half g_tval [C4*CDIM];
__device__ __align__(256) __half g_tout [CDIM*C4];
__device__ __align__(256) __half g_tsg1 [512*CDIM];
__device__ __align__(256) __half g_tsg2 [3072*512];
__device__ __align__(256) __half g_tbw  [(size_t)BIASNP*LATD];

// ---------------- PTX helpers ----------------
__device__ __forceinline__ uint32_t smem_u32(const void* p){
    uint32_t a;
    asm("{ .reg .u64 t; cvta.to.shared.u64 t, %1; cvt.u32.u64 %0, t; }" : "=r"(a) : "l"(p));
    return a;
}
__device__ __forceinline__ void cpa16(uint32_t s, const void* g){
    asm volatile("cp.async.cg.shared.global [%0], [%1], 16;" :: "r"(s), "l"(g));
}
#define CP_COMMIT() asm volatile("cp.async.commit_group;")
#define CP_WAIT2()  asm volatile("cp.async.wait_group 2;")
__device__ __forceinline__ void ldsm4(uint32_t* r, uint32_t addr){
    asm volatile("ldmatrix.sync.aligned.m8n8.x4.shared.b16 {%0,%1,%2,%3}, [%4];"
        : "=r"(r[0]),"=r"(r[1]),"=r"(r[2]),"=r"(r[3]) : "r"(addr));
}
__device__ __forceinline__ void mma16816(float* c, const uint32_t* a, uint32_t b0, uint32_t b1){
    asm volatile(
      "mma.sync.aligned.m16n8k16.row.col.f32.f16.f16.f32 "
      "{%0,%1,%2,%3},{%4,%5,%6,%7},{%8,%9},{%0,%1,%2,%3};"
      : "+f"(c[0]),"+f"(c[1]),"+f"(c[2]),"+f"(c[3])
      : "r"(a[0]),"r"(a[1]),"r"(a[2]),"r"(a[3]),"r"(b0),"r"(b1));
}
__device__ __forceinline__ float silu_f(float v){ return v/(1.f+expf(-v)); }

// smem geometry: rows of 32 halves padded to 40 halves (80B).
#define SROW   80
#define ASTG   (128*SROW)     // 10240 B per A stage
#define NSTAGE 4

// =====================================================================================
// fp16 GEMM: C[M,N](fp32) = A[M,K](fp16 row-major) @ Bt[N][K](fp16 K-major)^T
// Tile 128x128x32, 4-stage cp.async pipeline, ldmatrix + mma.m16n8k16.
// EPI: 0 = store, 1 = residual add. NGUARD: guard C cols < N.
// =====================================================================================
template<int EPI, bool NGUARD>
__global__ void __launch_bounds__(256,2)
gemm_h(const __half* __restrict__ A, const __half* __restrict__ Bt,
       float* __restrict__ C, int M, int N, int K, int lda, int ldc)
{
    extern __shared__ __align__(128) char dyn[];
    const uint32_t sA = smem_u32(dyn);
    const uint32_t sB = sA + NSTAGE*ASTG;

    const int tid = threadIdx.x, wid = tid>>5, lane = tid&31;
    const int wm = wid>>2, wn = wid&3;           // 2x4 warps, warp tile 64x32
    const size_t bm = (size_t)blockIdx.y*128;
    const size_t bn = (size_t)blockIdx.x*128;
    const int KT = K/32;

    float acc[4][4][4];
    #pragma unroll
    for (int i=0;i<4;i++) for (int j=0;j<4;j++) for (int r=0;r<4;r++) acc[i][j][r]=0.f;

    auto LOADS = [&](int s, int t){
        const uint32_t sa = sA + s*ASTG, sb = sB + s*ASTG;
        #pragma unroll
        for (int u=0;u<2;u++){
            int c = tid + u*256;
            int row = c>>2, col8 = (c&3)*8;
            cpa16(sa + row*SROW + col8*2, A  + (bm+row)*(size_t)lda + (size_t)t*32 + col8);
            cpa16(sb + row*SROW + col8*2, Bt + (bn+row)*(size_t)K   + (size_t)t*32 + col8);
        }
    };
    auto COMPUTE = [&](int s){
        const uint32_t sa = sA + s*ASTG, sb = sB + s*ASTG;
        #pragma unroll
        for (int kc=0;kc<2;kc++){
            uint32_t af[4][4], bf[2][4];
            #pragma unroll
            for (int i=0;i<4;i++){
                int r = wm*64 + i*16 + (lane&7) + ((lane>>3)&1)*8;
                int k = kc*16 + (lane>>4)*8;
                ldsm4(af[i], sa + r*SROW + k*2);
            }
            #pragma unroll
            for (int jj=0;jj<2;jj++){
                int n = wn*32 + jj*16 + ((lane>>4)<<3) + (lane&7);
                int k = kc*16 + ((lane>>3)&1)*8;
                ldsm4(bf[jj], sb + n*SROW + k*2);
            }
            #pragma unroll
            for (int i=0;i<4;i++)
              #pragma unroll
              for (int jj=0;jj<2;jj++){
                mma16816(acc[i][jj*2  ], af[i], bf[jj][0], bf[jj][1]);
                mma16816(acc[i][jj*2+1], af[i], bf[jj][2], bf[jj][3]);
              }
        }
    };

    LOADS(0,0); CP_COMMIT();
    if (KT>1) LOADS(1,1);
    CP_COMMIT();
    if (KT>2) LOADS(2,2);
    CP_COMMIT();
    for (int t=0;t<KT;t++){
        CP_WAIT2();
        __syncthreads();
        COMPUTE(t%NSTAGE);
        int nt = t+3;
        if (nt<KT) LOADS(nt%NSTAGE, nt);
        CP_COMMIT();
    }

    // epilogue
    const int r4 = lane>>2, c2 = (lane&3)*2;
    #pragma unroll
    for (int i=0;i<4;i++){
        size_t r0 = bm + wm*64 + i*16 + r4;
        float* Cp0 = C + r0*(size_t)ldc;
        float* Cp1 = Cp0 + 8*(size_t)ldc;
        #pragma unroll
        for (int j=0;j<4;j++){
            size_t col = bn + wn*32 + j*8 + c2;
            if (!NGUARD){
                float2* p0 = (float2*)(Cp0+col);
                float2* p1 = (float2*)(Cp1+col);
                float2 v0 = make_float2(acc[i][j][0], acc[i][j][1]);
                float2 v1 = make_float2(acc[i][j][2], acc[i][j][3]);
                if (EPI==1){ float2 o0=*p0, o1=*p1; v0.x+=o0.x; v0.y+=o0.y; v1.x+=o1.x; v1.y+=o1.y; }
                *p0 = v0; *p1 = v1;
            } else {
                if ((long long)col < N){
                    float v = acc[i][j][0]; if (EPI==1) v += Cp0[col]; Cp0[col]=v;
                    v = acc[i][j][2]; if (EPI==1) v += Cp1[col]; Cp1[col]=v;
                }
                if ((long long)col+1 < N){
                    float v = acc[i][j][1]; if (EPI==1) v += Cp0[col+1]; Cp0[col+1]=v;
                    v = acc[i][j][3]; if (EPI==1) v += Cp1[col+1]; Cp1[col+1]=v;
                }
            }
        }
    }
}

// =====================================================================================
// dual fp16 GEMM: C(fp16) = (A@G^T) * silu(A@V^T). Tile 128x64x32.
// =====================================================================================
__global__ void __launch_bounds__(256,2)
gemm_dual_h(const __half* __restrict__ A, const __half* __restrict__ Gt,
            const __half* __restrict__ Vt, __half* __restrict__ C,
            int M, int N, int K, int lda, int ldc)
{
    extern __shared__ __align__(128) char dyn[];
    const uint32_t sA = smem_u32(dyn);
    const uint32_t sG = sA + NSTAGE*ASTG;
    const uint32_t sV = sG + NSTAGE*(64*SROW);

    const int tid = threadIdx.x, wid = tid>>5, lane = tid&31;
    const int wm = wid>>2, wn = wid&3;           // warp tile 64x16
    const size_t bm = (size_t)blockIdx.y*128;
    const size_t bn = (size_t)blockIdx.x*64;
    const int KT = K/32;

    float ag[4][2][4], av[4][2][4];
    #pragma unroll
    for (int i=0;i<4;i++) for (int j=0;j<2;j++) for (int r=0;r<4;r++){ ag[i][j][r]=0.f; av[i][j][r]=0.f; }

    auto LOADS = [&](int s, int t){
        const uint32_t sa = sA + s*ASTG;
        const uint32_t sg = sG + s*(64*SROW);
        const uint32_t sv = sV + s*(64*SROW);
        #pragma unroll
        for (int u=0;u<2;u++){
            int c = tid + u*256;
            int row = c>>2, col8 = (c&3)*8;
            cpa16(sa + row*SROW + col8*2, A + (bm+row)*(size_t)lda + (size_t)t*32 + col8);
        }
        {
            int row = tid>>2, col8 = (tid&3)*8;
            cpa16(sg + row*SROW + col8*2, Gt + (bn+row)*(size_t)K + (size_t)t*32 + col8);
            cpa16(sv + row*SROW + col8*2, Vt + (bn+row)*(size_t)K + (size_t)t*32 + col8);
        }
    };
    auto COMPUTE = [&](int s){
        const uint32_t sa = sA + s*ASTG;
        const uint32_t sg = sG + s*(64*SROW);
        const uint32_t sv = sV + s*(64*SROW);
        #pragma unroll
        for (int kc=0;kc<2;kc++){
            uint32_t af[4][4], gf[4], vf[4];
            #pragma unroll
            for (int i=0;i<4;i++){
                int r = wm*64 + i*16 + (lane&7) + ((lane>>3)&1)*8;
                int k = kc*16 + (lane>>4)*8;
                ldsm4(af[i], sa + r*SROW + k*2);
            }
            {
                int n = wn*16 + ((lane>>4)<<3) + (lane&7);
                int k = kc*16 + ((lane>>3)&1)*8;
                ldsm4(gf, sg + n*SROW + k*2);
                ldsm4(vf, sv + n*SROW + k*2);
            }
            #pragma unroll
            for (int i=0;i<4;i++){
                mma16816(ag[i][0], af[i], gf[0], gf[1]);
                mma16816(ag[i][1], af[i], gf[2], gf[3]);
                mma16816(av[i][0], af[i], vf[0], vf[1]);
                mma16816(av[i][1], af[i], vf[2], vf[3]);
            }
        }
    };

    LOADS(0,0); CP_COMMIT();
    if (KT>1) LOADS(1,1);
    CP_COMMIT();
    if (KT>2) LOADS(2,2);
    CP_COMMIT();
    for (int t=0;t<KT;t++){
        CP_WAIT2();
        __syncthreads();
        COMPUTE(t%NSTAGE);
        int nt = t+3;
        if (nt<KT) LOADS(nt%NSTAGE, nt);
        CP_COMMIT();
    }

    const int r4 = lane>>2, c2 = (lane&3)*2;
    #pragma unroll
    for (int i=0;i<4;i++){
        size_t r0 = bm + wm*64 + i*16 + r4;
        __half* Cp0 = C + r0*(size_t)ldc;
        __half* Cp1 = Cp0 + 8*(size_t)ldc;
        #pragma unroll
        for (int j=0;j<2;j++){
            size_t col = bn + wn*16 + j*8 + c2;
            __half2 v0 = __floats2half2_rn(ag[i][j][0]*silu_f(av[i][j][0]),
                                           ag[i][j][1]*silu_f(av[i][j][1]));
            __half2 v1 = __floats2half2_rn(ag[i][j][2]*silu_f(av[i][j][2]),
                                           ag[i][j][3]*silu_f(av[i][j][3]));
            *(__half2*)(Cp0+col) = v0;
            *(__half2*)(Cp1+col) = v1;
        }
    }
}

// ---------------- LayerNorm (fp32 in, fp16 out; optional silu) ----------------
__global__ void ln_h_kernel(const float* __restrict__ in, __half* __restrict__ out,
                            const float* __restrict__ gamma, const float* __restrict__ beta,
                            int W, int dosilu)
{
    size_t row = blockIdx.x;
    const float* x = in + row*(size_t)W;
    __half* y = out + row*(size_t)W;
    float s=0.f, s2=0.f;
    for (int i=threadIdx.x; i<W; i+=blockDim.x){ float v=x[i]; s+=v; s2+=v*v; }
    __shared__ float rs[32], rs2[32];
    int lane = threadIdx.x & 31, wid = threadIdx.x >> 5;
    #pragma unroll
    for (int o=16;o;o>>=1){ s += __shfl_xor_sync(0xffffffffu,s,o); s2 += __shfl_xor_sync(0xffffffffu,s2,o); }
    if (lane==0){ rs[wid]=s; rs2[wid]=s2; }
    __syncthreads();
    if (wid==0){
        float a  = (lane<8)? rs[lane]  : 0.f;
        float a2 = (lane<8)? rs2[lane] : 0.f;
        #pragma unroll
        for (int o=4;o;o>>=1){ a += __shfl_xor_sync(0xffffffffu,a,o); a2 += __shfl_xor_sync(0xffffffffu,a2,o); }
        if (lane==0){ rs[0]=a; rs2[0]=a2; }
    }
    __syncthreads();
    float mean = rs[0]/(float)W;
    float var  = rs2[0]/(float)W - mean*mean;
    float rstd = rsqrtf(var + 1e-5f);
    for (int i=threadIdx.x; i<W; i+=blockDim.x){
        float v = (x[i]-mean)*rstd*gamma[i] + beta[i];
        if (dosilu) v = silu_f(v);
        y[i] = __float2half(v);
    }
}

// ---------------- QK LayerNorm over DH=64 (one warp per (row, q/k, head)) -----------
__global__ void qknorm_kernel(float* __restrict__ qkv,
                              const float* __restrict__ qg, const float* __restrict__ qb,
                              const float* __restrict__ kg, const float* __restrict__ kb)
{
    int w = (blockIdx.x*blockDim.x + threadIdx.x) >> 5;
    int lane = threadIdx.x & 31;
    if (w >= ROWS*24) return;
    int r = w / 24, rem = w % 24, t = rem / 12, h = rem % 12;
    float* p = qkv + (size_t)r*C3 + t*CDIM + h*DHEAD;
    float v0 = p[lane], v1 = p[lane+32];
    float s = v0 + v1;
    #pragma unroll
    for (int o=16;o;o>>=1) s += __shfl_xor_sync(0xffffffffu,s,o);
    float mean = s * (1.f/64.f);
    float d0 = v0-mean, d1 = v1-mean;
    float s2 = d0*d0 + d1*d1;
    #pragma unroll
    for (int o=16;o;o>>=1) s2 += __shfl_xor_sync(0xffffffffu,s2,o);
    float rstd = rsqrtf(s2*(1.f/64.f) + 1e-5f);
    const float* gg = t ? kg : qg;
    const float* bb = t ? kb : qb;
    float scale = t ? 1.f : 0.125f;
    p[lane]    = (d0*rstd*gg[lane]    + bb[lane]   ) * scale;
    p[lane+32] = (d1*rstd*gg[lane+32] + bb[lane+32]) * scale;
}

// ---------------- fused attention per (b,h), 4x4 register tiling; fp16 o ------------
// smem: qs[65][64], vs[65][64], kt[64][68], S[65][68]  = 68368 B
__global__ void __launch_bounds__(256)
attn_kernel(const float* __restrict__ qkv, const float* __restrict__ bias,
            __half* __restrict__ o)
{
    int bh = blockIdx.x;
    int b  = bh / NHEADS, hh = bh % NHEADS;
    extern __shared__ float sm[];
    float* qs = sm;                 // [65][64]
    float* vs = qs + NTOK*DHEAD;    // [65][64]
    float* kt = vs + NTOK*DHEAD;    // [64][68]
    float* S  = kt + DHEAD*68;      // [65][68]
    const int tid = threadIdx.x;

    // load q, v row-major; k transposed (stride 68)
    for (int idx=tid; idx<NTOK*16; idx+=256){
        int n = idx>>4, d4 = (idx&15)<<2;
        const float* base = qkv + (size_t)(b*NTOK+n)*C3 + hh*DHEAD;
        float4 q4 = *(const float4*)(base + d4);
        float4 k4 = *(const float4*)(base + CDIM + d4);
        float4 v4 = *(const float4*)(base + 2*CDIM + d4);
        *(float4*)&qs[n*64 + d4] = q4;
        *(float4*)&vs[n*64 + d4] = v4;
        kt[(d4  )*68 + n] = k4.x;
        kt[(d4+1)*68 + n] = k4.y;
        kt[(d4+2)*68 + n] = k4.z;
        kt[(d4+3)*68 + n] = k4.w;
    }
    __syncthreads();

    const float* bb = bias + (size_t)bh*BIASN;
    // S main tile: 64x64 region, 16x16 threads x (4x4 each)
    {
        const int it = tid>>4, jt = tid&15;
        const int i0 = it*4, j0 = jt*4;
        float acc[4][4];
        #pragma unroll
        for (int r=0;r<4;r++)
            #pragma unroll
            for (int c=0;c<4;c++)
                acc[r][c] = bb[(i0+r)*NTOK + j0 + c];
        #pragma unroll 8
        for (int d=0; d<DHEAD; d++){
            float4 kv = *(float4*)&kt[d*68 + j0];
            float q0 = qs[(i0+0)*64 + d];
            float q1 = qs[(i0+1)*64 + d];
            float q2 = qs[(i0+2)*64 + d];
            float q3 = qs[(i0+3)*64 + d];
            acc[0][0]+=q0*kv.x; acc[0][1]+=q0*kv.y; acc[0][2]+=q0*kv.z; acc[0][3]+=q0*kv.w;
            acc[1][0]+=q1*kv.x; acc[1][1]+=q1*kv.y; acc[1][2]+=q1*kv.z; acc[1][3]+=q1*kv.w;
            acc[2][0]+=q2*kv.x; acc[2][1]+=q2*kv.y; acc[2][2]+=q2*kv.z; acc[2][3]+=q2*kv.w;
            acc[3][0]+=q3*kv.x; acc[3][1]+=q3*kv.y; acc[3][2]+=q3*kv.z; acc[3][3]+=q3*kv.w;
        }
        #pragma unroll
        for (int r=0;r<4;r++)
            *(float4*)&S[(i0+r)*68 + j0] =
                make_float4(acc[r][0],acc[r][1],acc[r][2],acc[r][3]);
    }
    // S edges: row 64 (j=0..64) and col 64 (i=0..63)
    if (tid < 129){
        int i, j;
        if (tid < NTOK){ i = 64; j = tid; }
        else           { i = tid - NTOK; j = 64; }
        float a = bb[i*NTOK + j];
        #pragma unroll 16
        for (int d=0; d<DHEAD; d++) a += qs[i*64 + d] * kt[d*68 + j];
        S[i*68 + j] = a;
    }
    __syncthreads();

    // softmax over rows (cols 0..64)
    {
        int wid = tid >> 5, lane = tid & 31;
        for (int i=wid; i<NTOK; i+=8){
            float* Sr = S + i*68;
            float m = -1e30f;
            for (int j=lane; j<NTOK; j+=32) m = fmaxf(m, Sr[j]);
            #pragma unroll
            for (int off=16;off;off>>=1) m = fmaxf(m, __shfl_xor_sync(0xffffffffu,m,off));
            float sum = 0.f;
            for (int j=lane; j<NTOK; j+=32){ float e = expf(Sr[j]-m); Sr[j]=e; sum+=e; }
            #pragma unroll
            for (int off=16;off;off>>=1) sum += __shfl_xor_sync(0xffffffffu,sum,off);
            float inv = 1.f/sum;
            for (int j=lane; j<NTOK; j+=32) Sr[j] *= inv;
        }
    }
    __syncthreads();

    // O = P @ V : main 64x64 region tiled 4x4
    {
        const int it = tid>>4, dt = tid&15;
        const int i0 = it*4, d0 = dt*4;
        float acc[4][4];
        #pragma unroll
        for (int r=0;r<4;r++)
            #pragma unroll
            for (int c=0;c<4;c++) acc[r][c]=0.f;
        #pragma unroll 5
        for (int j=0; j<NTOK; j++){
            float4 vv = *(float4*)&vs[j*64 + d0];
            float s0 = S[(i0+0)*68 + j];
            float s1 = S[(i0+1)*68 + j];
            float s2 = S[(i0+2)*68 + j];
            float s3 = S[(i0+3)*68 + j];
            acc[0][0]+=s0*vv.x; acc[0][1]+=s0*vv.y; acc[0][2]+=s0*vv.z; acc[0][3]+=s0*vv.w;
            acc[1][0]+=s1*vv.x; acc[1][1]+=s1*vv.y; acc[1][2]+=s1*vv.z; acc[1][3]+=s1*vv.w;
            acc[2][0]+=s2*vv.x; acc[2][1]+=s2*vv.y; acc[2][2]+=s2*vv.z; acc[2][3]+=s2*vv.w;
            acc[3][0]+=s3*vv.x; acc[3][1]+=s3*vv.y; acc[3][2]+=s3*vv.z; acc[3][3]+=s3*vv.w;
        }
        #pragma unroll
        for (int r=0;r<4;r++){
            __half2 h0 = __floats2half2_rn(acc[r][0], acc[r][1]);
            __half2 h1 = __floats2half2_rn(acc[r][2], acc[r][3]);
            __half* op = o + (size_t)(b*NTOK + i0 + r)*CDIM + hh*DHEAD + d0;
            *(__half2*)(op)   = h0;
            *(__half2*)(op+2) = h1;
        }
    }
    // O edge row i=64
    if (tid < DHEAD){
        int d = tid;
        float a = 0.f;
        #pragma unroll 5
        for (int j=0; j<NTOK; j++) a += S[64*68 + j] * vs[j*64 + d];
        o[(size_t)(b*NTOK + 64)*CDIM + hh*DHEAD + d] = __float2half(a);
    }
}

// ---------------- weight transpose: fp32 in[K][N] -> fp16 out[Npad][K] --------------
__global__ void transpose_pad_h(const float* __restrict__ in, __half* __restrict__ out,
                                int K, int N, int Npad)
{
    __shared__ float t[32][33];
    int kb = blockIdx.y*32, nb = blockIdx.x*32;
    #pragma unroll
    for (int i=0;i<4;i++){
        int k = kb + threadIdx.y + i*8, n = nb + threadIdx.x;
        t[threadIdx.y+i*8][threadIdx.x] = (k<K && n<N) ? in[(size_t)k*N + n] : 0.f;
    }
    __syncthreads();
    #pragma unroll
    for (int i=0;i<4;i++){
        int n = nb + threadIdx.y + i*8, k = kb + threadIdx.x;
        if (n<Npad && k<K) out[(size_t)n*K + k] = __float2half(t[threadIdx.x][threadIdx.y+i*8]);
    }
}

// ---------------- host ----------------
static inline void tlaunch(const float* in, __half* out, int K, int N, int Npad){
    transpose_pad_h<<<dim3((Npad+31)/32,(K+31)/32), dim3(32,8)>>>(in, out, K, N, Npad);
}

extern "C" void kernel_launch(void* const* d_in, const int* in_sizes, int n_in,
                              void* d_out, int out_size)
{
    (void)in_sizes; (void)n_in; (void)out_size;
    const float* ln1_g  = (const float*)d_in[1];
    const float* ln1_b  = (const float*)d_in[2];
    const float* qkv_w  = (const float*)d_in[3];
    const float* proj_w = (const float*)d_in[4];
    const float* qn_g   = (const float*)d_in[5];
    const float* qn_b   = (const float*)d_in[6];
    const float* kn_g   = (const float*)d_in[7];
    const float* kn_b   = (const float*)d_in[8];
    const float* sg_w1  = (const float*)d_in[9];
    const float* sg1g   = (const float*)d_in[10];
    const float* sg1b   = (const float*)d_in[11];
    const float* sg_w2  = (const float*)d_in[12];
    const float* sg2g   = (const float*)d_in[13];
    const float* sg2b   = (const float*)d_in[14];
    const float* bw     = (const float*)d_in[15];
    const float* ln2_g  = (const float*)d_in[16];
    const float* ln2_b  = (const float*)d_in[17];
    const float* gate_w = (const float*)d_in[18];
    const float* value_w= (const float*)d_in[19];
    const float* out_w  = (const float*)d_in[20];

    float* X = (float*)d_out;

    void *ph,*pqkv,*po,*pgated,*pbias,*psg1,*psg1h,*psg2,*psg2h;
    void *ptqkv,*ptproj,*ptgate,*ptval,*ptout,*ptsg1,*ptsg2,*ptbw;
    cudaGetSymbolAddress(&ph,g_h); cudaGetSymbolAddress(&pqkv,g_qkv);
    cudaGetSymbolAddress(&po,g_o); cudaGetSymbolAddress(&pgated,g_gated);
    cudaGetSymbolAddress(&pbias,g_bias);
    cudaGetSymbolAddress(&psg1,g_sg1); cudaGetSymbolAddress(&psg1h,g_sg1h);
    cudaGetSymbolAddress(&psg2,g_sg2); cudaGetSymbolAddress(&psg2h,g_sg2h);
    cudaGetSymbolAddress(&ptqkv,g_tqkv); cudaGetSymbolAddress(&ptproj,g_tproj);
    cudaGetSymbolAddress(&ptgate,g_tgate); cudaGetSymbolAddress(&ptval,g_tval);
    cudaGetSymbolAddress(&ptout,g_tout); cudaGetSymbolAddress(&ptsg1,g_tsg1);
    cudaGetSymbolAddress(&ptsg2,g_tsg2); cudaGetSymbolAddress(&ptbw,g_tbw);
    __half* h=(__half*)ph; float* qkv=(float*)pqkv; __half* o=(__half*)po;
    __half* gated=(__half*)pgated; float* bias=(float*)pbias;
    float* sg1=(float*)psg1; __half* sg1h=(__half*)psg1h;
    float* sg2=(float*)psg2; __half* sg2h=(__half*)psg2h;
    __half* tqkv=(__half*)ptqkv; __half* tproj=(__half*)ptproj; __half* tgate=(__half*)ptgate;
    __half* tval=(__half*)ptval; __half* tout=(__half*)ptout; __half* tsg1=(__half*)ptsg1;
    __half* tsg2=(__half*)ptsg2; __half* tbw=(__half*)ptbw;

    const int attn_smem = (NTOK*DHEAD + NTOK*DHEAD + DHEAD*68 + NTOK*68) * 4;  // 68368
    cudaFuncSetAttribute(attn_kernel, cudaFuncAttributeMaxDynamicSharedMemorySize, attn_smem);
    const int g_smem = 2*NSTAGE*ASTG;                  // 81920
    const int d_smem = NSTAGE*ASTG + 2*NSTAGE*64*SROW; // 81920
    cudaFuncSetAttribute(gemm_h<0,false>, cudaFuncAttributeMaxDynamicSharedMemorySize, g_smem);
    cudaFuncSetAttribute(gemm_h<1,false>, cudaFuncAttributeMaxDynamicSharedMemorySize, g_smem);
    cudaFuncSetAttribute(gemm_h<0,true>,  cudaFuncAttributeMaxDynamicSharedMemorySize, g_smem);
    cudaFuncSetAttribute(gemm_dual_h,     cudaFuncAttributeMaxDynamicSharedMemorySize, d_smem);

    cudaMemcpyAsync(X, d_in[0], sizeof(float)*(size_t)ROWS*CDIM, cudaMemcpyDeviceToDevice);

    for (int l=0; l<NUM_LAYERS; l++){
        // fp16 K-major weights for this layer
        tlaunch(qkv_w  + (size_t)l*CDIM*C3,   tqkv,  CDIM, C3,   C3);
        tlaunch(proj_w + (size_t)l*CDIM*CDIM, tproj, CDIM, CDIM, CDIM);
        tlaunch(gate_w + (size_t)l*CDIM*C4,   tgate, CDIM, C4,   C4);
        tlaunch(value_w+ (size_t)l*CDIM*C4,   tval,  CDIM, C4,   C4);
        tlaunch(out_w  + (size_t)l*C4*CDIM,   tout,  C4,   CDIM, CDIM);
        tlaunch(sg_w1  + (size_t)l*CDIM*512,  tsg1,  CDIM, 512,  512);
        tlaunch(sg_w2  + (size_t)l*512*3072,  tsg2,  512,  3072, 3072);
        tlaunch(bw     + (size_t)l*LATD*BIASN,tbw,   LATD, BIASN, BIASNP);

        // h = LN1(x)  (fp16 out)
        ln_h_kernel<<<ROWS,256>>>(X, h, ln1_g+(size_t)l*CDIM, ln1_b+(size_t)l*CDIM, CDIM, 0);
        // qkv = h @ qkv_w
        gemm_h<0,false><<<dim3(C3/128, ROWS/128), 256, g_smem>>>(
            h, tqkv, qkv, ROWS, C3, CDIM, CDIM, C3);
        // q,k norm (+ q scale) in place
        qknorm_kernel<<<(ROWS*24)/8, 256>>>(qkv,
            qn_g+(size_t)l*DHEAD, qn_b+(size_t)l*DHEAD,
            kn_g+(size_t)l*DHEAD, kn_b+(size_t)l*DHEAD);
        // structure-gate MLP (cls rows of h, lda = NTOK*CDIM)
        gemm_h<0,false><<<dim3(4,4), 256, g_smem>>>(
            h, tsg1, sg1, 512, 512, CDIM, NTOK*CDIM, 512);
        ln_h_kernel<<<512,256>>>(sg1, sg1h, sg1g+(size_t)l*512, sg1b+(size_t)l*512, 512, 1);
        gemm_h<0,false><<<dim3(24,4), 256, g_smem>>>(
            sg1h, tsg2, sg2, 512, 3072, 512, 512, 3072);
        ln_h_kernel<<<512,256>>>(sg2, sg2h, sg2g+(size_t)l*3072, sg2b+(size_t)l*3072, 3072, 0);
        // bias = lat2(B*H,256) @ bw(256,4225)
        gemm_h<0,true><<<dim3(BIASNP/128, BHD/128), 256, g_smem>>>(
            sg2h, tbw, bias, BHD, BIASN, LATD, LATD, BIASN);
        // fused attention (fp16 o)
        attn_kernel<<<BHD, 256, attn_smem>>>(qkv, bias, o);
        // x += o @ proj_w
        gemm_h<1,false><<<dim3(CDIM/128, ROWS/128), 256, g_smem>>>(
            o, tproj, X, ROWS, CDIM, CDIM, CDIM, CDIM);
        // h2 = LN2(x)
        ln_h_kernel<<<ROWS,256>>>(X, h, ln2_g+(size_t)l*CDIM, ln2_b+(size_t)l*CDIM, CDIM, 0);
        // gated = (h2@gate_w) * silu(h2@value_w)   (fp16 out)
        gemm_dual_h<<<dim3(C4/64, ROWS/128), 256, d_smem>>>(
            h, tgate, tval, gated, ROWS, C4, CDIM, CDIM, C4);
        // x += gated @ out_w
        gemm_h<1,false><<<dim3(CDIM/128, ROWS/128), 256, g_smem>>>(
            gated, tout, X, ROWS, CDIM, C4, C4, CDIM);
    }
}

// round 11
// speedup vs baseline: 3.0312x; 1.0489x over previous
#include <cuda_runtime.h>
#include <cuda_fp16.h>
#include <math.h>
#include <stdint.h>

#define NUM_LAYERS 6
#define CDIM 768
#define NHEADS 12
#define DHEAD 64
#define LATD 256
#define NTOK 65
#define BATCH 512
#define ROWS (BATCH*NTOK)          // 33280
#define C3 (3*CDIM)                // 2304
#define C4 (4*CDIM)                // 3072
#define BHD (BATCH*NHEADS)         // 6144
#define BIASN (NTOK*NTOK)          // 4225
#define BIASNP 4352                // padded to %128

// ---------------- scratch (static device allocations; no cudaMalloc) ----------------
__device__ __align__(256) __half g_h    [(size_t)ROWS*CDIM];
__device__ __align__(256) float  g_qkv  [(size_t)ROWS*C3];
__device__ __align__(256) __half g_o    [(size_t)ROWS*CDIM];
__device__ __align__(256) __half g_gated[(size_t)ROWS*C4];
__device__ __align__(256) float  g_bias [(size_t)BHD*BIASN];
__device__ __align__(256) float  g_sg1  [512*512];
__device__ __align__(256) __half g_sg1h [512*512];
__device__ __align__(256) float  g_sg2  [512*3072];
__device__ __align__(256) __half g_sg2h [512*3072];
// double-buffered transposed (K-major, [N][K]) fp16 weights
__device__ __align__(256) __half g_tqkv [2][C3*CDIM];
__device__ __align__(256) __half g_tproj[2][CDIM*CDIM];
__device__ __align__(256) __half g_tgate[2][C4*CDIM];
__device__ __align__(256) __half g_tval [2][C4*CDIM];
__device__ __align__(256) __half g_tout [2][CDIM*C4];
__device__ __align__(256) __half g_tsg1 [2][512*CDIM];
__device__ __align__(256) __half g_tsg2 [2][3072*512];
__device__ __align__(256) __half g_tbw  [2][(size_t)BIASNP*LATD];

// ---------------- PTX helpers ----------------
__device__ __forceinline__ uint32_t smem_u32(const void* p){
    uint32_t a;
    asm("{ .reg .u64 t; cvta.to.shared.u64 t, %1; cvt.u32.u64 %0, t; }" : "=r"(a) : "l"(p));
    return a;
}
__device__ __forceinline__ void cpa16(uint32_t s, const void* g){
    asm volatile("cp.async.cg.shared.global [%0], [%1], 16;" :: "r"(s), "l"(g));
}
#define CP_COMMIT() asm volatile("cp.async.commit_group;")
#define CP_WAIT2()  asm volatile("cp.async.wait_group 2;")
__device__ __forceinline__ void ldsm4(uint32_t* r, uint32_t addr){
    asm volatile("ldmatrix.sync.aligned.m8n8.x4.shared.b16 {%0,%1,%2,%3}, [%4];"
        : "=r"(r[0]),"=r"(r[1]),"=r"(r[2]),"=r"(r[3]) : "r"(addr));
}
__device__ __forceinline__ void mma16816(float* c, const uint32_t* a, uint32_t b0, uint32_t b1){
    asm volatile(
      "mma.sync.aligned.m16n8k16.row.col.f32.f16.f16.f32 "
      "{%0,%1,%2,%3},{%4,%5,%6,%7},{%8,%9},{%0,%1,%2,%3};"
      : "+f"(c[0]),"+f"(c[1]),"+f"(c[2]),"+f"(c[3])
      : "r"(a[0]),"r"(a[1]),"r"(a[2]),"r"(a[3]),"r"(b0),"r"(b1));
}
__device__ __forceinline__ float silu_f(float v){ return v/(1.f+expf(-v)); }

#define SROW   80
#define ASTG   (128*SROW)
#define NSTAGE 4

// =====================================================================================
// fp16 GEMM: C[M,N](fp32) = A[M,K](fp16 row-major) @ Bt[N][K](fp16 K-major)^T
// =====================================================================================
template<int EPI, bool NGUARD>
__global__ void __launch_bounds__(256,2)
gemm_h(const __half* __restrict__ A, const __half* __restrict__ Bt,
       float* __restrict__ C, int M, int N, int K, int lda, int ldc)
{
    extern __shared__ __align__(128) char dyn[];
    const uint32_t sA = smem_u32(dyn);
    const uint32_t sB = sA + NSTAGE*ASTG;

    const int tid = threadIdx.x, wid = tid>>5, lane = tid&31;
    const int wm = wid>>2, wn = wid&3;
    const size_t bm = (size_t)blockIdx.y*128;
    const size_t bn = (size_t)blockIdx.x*128;
    const int KT = K/32;

    float acc[4][4][4];
    #pragma unroll
    for (int i=0;i<4;i++) for (int j=0;j<4;j++) for (int r=0;r<4;r++) acc[i][j][r]=0.f;

    auto LOADS = [&](int s, int t){
        const uint32_t sa = sA + s*ASTG, sb = sB + s*ASTG;
        #pragma unroll
        for (int u=0;u<2;u++){
            int c = tid + u*256;
            int row = c>>2, col8 = (c&3)*8;
            cpa16(sa + row*SROW + col8*2, A  + (bm+row)*(size_t)lda + (size_t)t*32 + col8);
            cpa16(sb + row*SROW + col8*2, Bt + (bn+row)*(size_t)K   + (size_t)t*32 + col8);
        }
    };
    auto COMPUTE = [&](int s){
        const uint32_t sa = sA + s*ASTG, sb = sB + s*ASTG;
        #pragma unroll
        for (int kc=0;kc<2;kc++){
            uint32_t af[4][4], bf[2][4];
            #pragma unroll
            for (int i=0;i<4;i++){
                int r = wm*64 + i*16 + (lane&7) + ((lane>>3)&1)*8;
                int k = kc*16 + (lane>>4)*8;
                ldsm4(af[i], sa + r*SROW + k*2);
            }
            #pragma unroll
            for (int jj=0;jj<2;jj++){
                int n = wn*32 + jj*16 + ((lane>>4)<<3) + (lane&7);
                int k = kc*16 + ((lane>>3)&1)*8;
                ldsm4(bf[jj], sb + n*SROW + k*2);
            }
            #pragma unroll
            for (int i=0;i<4;i++)
              #pragma unroll
              for (int jj=0;jj<2;jj++){
                mma16816(acc[i][jj*2  ], af[i], bf[jj][0], bf[jj][1]);
                mma16816(acc[i][jj*2+1], af[i], bf[jj][2], bf[jj][3]);
              }
        }
    };

    LOADS(0,0); CP_COMMIT();
    if (KT>1) LOADS(1,1);
    CP_COMMIT();
    if (KT>2) LOADS(2,2);
    CP_COMMIT();
    for (int t=0;t<KT;t++){
        CP_WAIT2();
        __syncthreads();
        COMPUTE(t%NSTAGE);
        int nt = t+3;
        if (nt<KT) LOADS(nt%NSTAGE, nt);
        CP_COMMIT();
    }

    const int r4 = lane>>2, c2 = (lane&3)*2;
    #pragma unroll
    for (int i=0;i<4;i++){
        size_t r0 = bm + wm*64 + i*16 + r4;
        float* Cp0 = C + r0*(size_t)ldc;
        float* Cp1 = Cp0 + 8*(size_t)ldc;
        #pragma unroll
        for (int j=0;j<4;j++){
            size_t col = bn + wn*32 + j*8 + c2;
            if (!NGUARD){
                float2* p0 = (float2*)(Cp0+col);
                float2* p1 = (float2*)(Cp1+col);
                float2 v0 = make_float2(acc[i][j][0], acc[i][j][1]);
                float2 v1 = make_float2(acc[i][j][2], acc[i][j][3]);
                if (EPI==1){ float2 o0=*p0, o1=*p1; v0.x+=o0.x; v0.y+=o0.y; v1.x+=o1.x; v1.y+=o1.y; }
                *p0 = v0; *p1 = v1;
            } else {
                if ((long long)col < N){
                    float v = acc[i][j][0]; if (EPI==1) v += Cp0[col]; Cp0[col]=v;
                    v = acc[i][j][2]; if (EPI==1) v += Cp1[col]; Cp1[col]=v;
                }
                if ((long long)col+1 < N){
                    float v = acc[i][j][1]; if (EPI==1) v += Cp0[col+1]; Cp0[col+1]=v;
                    v = acc[i][j][3]; if (EPI==1) v += Cp1[col+1]; Cp1[col+1]=v;
                }
            }
        }
    }
}

// =====================================================================================
// dual fp16 GEMM: C(fp16) = (A@G^T) * silu(A@V^T). Tile 128x64x32.
// =====================================================================================
__global__ void __launch_bounds__(256,2)
gemm_dual_h(const __half* __restrict__ A, const __half* __restrict__ Gt,
            const __half* __restrict__ Vt, __half* __restrict__ C,
            int M, int N, int K, int lda, int ldc)
{
    extern __shared__ __align__(128) char dyn[];
    const uint32_t sA = smem_u32(dyn);
    const uint32_t sG = sA + NSTAGE*ASTG;
    const uint32_t sV = sG + NSTAGE*(64*SROW);

    const int tid = threadIdx.x, wid = tid>>5, lane = tid&31;
    const int wm = wid>>2, wn = wid&3;
    const size_t bm = (size_t)blockIdx.y*128;
    const size_t bn = (size_t)blockIdx.x*64;
    const int KT = K/32;

    float ag[4][2][4], av[4][2][4];
    #pragma unroll
    for (int i=0;i<4;i++) for (int j=0;j<2;j++) for (int r=0;r<4;r++){ ag[i][j][r]=0.f; av[i][j][r]=0.f; }

    auto LOADS = [&](int s, int t){
        const uint32_t sa = sA + s*ASTG;
        const uint32_t sg = sG + s*(64*SROW);
        const uint32_t sv = sV + s*(64*SROW);
        #pragma unroll
        for (int u=0;u<2;u++){
            int c = tid + u*256;
            int row = c>>2, col8 = (c&3)*8;
            cpa16(sa + row*SROW + col8*2, A + (bm+row)*(size_t)lda + (size_t)t*32 + col8);
        }
        {
            int row = tid>>2, col8 = (tid&3)*8;
            cpa16(sg + row*SROW + col8*2, Gt + (bn+row)*(size_t)K + (size_t)t*32 + col8);
            cpa16(sv + row*SROW + col8*2, Vt + (bn+row)*(size_t)K + (size_t)t*32 + col8);
        }
    };
    auto COMPUTE = [&](int s){
        const uint32_t sa = sA + s*ASTG;
        const uint32_t sg = sG + s*(64*SROW);
        const uint32_t sv = sV + s*(64*SROW);
        #pragma unroll
        for (int kc=0;kc<2;kc++){
            uint32_t af[4][4], gf[4], vf[4];
            #pragma unroll
            for (int i=0;i<4;i++){
                int r = wm*64 + i*16 + (lane&7) + ((lane>>3)&1)*8;
                int k = kc*16 + (lane>>4)*8;
                ldsm4(af[i], sa + r*SROW + k*2);
            }
            {
                int n = wn*16 + ((lane>>4)<<3) + (lane&7);
                int k = kc*16 + ((lane>>3)&1)*8;
                ldsm4(gf, sg + n*SROW + k*2);
                ldsm4(vf, sv + n*SROW + k*2);
            }
            #pragma unroll
            for (int i=0;i<4;i++){
                mma16816(ag[i][0], af[i], gf[0], gf[1]);
                mma16816(ag[i][1], af[i], gf[2], gf[3]);
                mma16816(av[i][0], af[i], vf[0], vf[1]);
                mma16816(av[i][1], af[i], vf[2], vf[3]);
            }
        }
    };

    LOADS(0,0); CP_COMMIT();
    if (KT>1) LOADS(1,1);
    CP_COMMIT();
    if (KT>2) LOADS(2,2);
    CP_COMMIT();
    for (int t=0;t<KT;t++){
        CP_WAIT2();
        __syncthreads();
        COMPUTE(t%NSTAGE);
        int nt = t+3;
        if (nt<KT) LOADS(nt%NSTAGE, nt);
        CP_COMMIT();
    }

    const int r4 = lane>>2, c2 = (lane&3)*2;
    #pragma unroll
    for (int i=0;i<4;i++){
        size_t r0 = bm + wm*64 + i*16 + r4;
        __half* Cp0 = C + r0*(size_t)ldc;
        __half* Cp1 = Cp0 + 8*(size_t)ldc;
        #pragma unroll
        for (int j=0;j<2;j++){
            size_t col = bn + wn*16 + j*8 + c2;
            __half2 v0 = __floats2half2_rn(ag[i][j][0]*silu_f(av[i][j][0]),
                                           ag[i][j][1]*silu_f(av[i][j][1]));
            __half2 v1 = __floats2half2_rn(ag[i][j][2]*silu_f(av[i][j][2]),
                                           ag[i][j][3]*silu_f(av[i][j][3]));
            *(__half2*)(Cp0+col) = v0;
            *(__half2*)(Cp1+col) = v1;
        }
    }
}

// ---------------- LayerNorm (fp32 in, fp16 out; optional silu) ----------------
__global__ void ln_h_kernel(const float* __restrict__ in, __half* __restrict__ out,
                            const float* __restrict__ gamma, const float* __restrict__ beta,
                            int W, int dosilu)
{
    size_t row = blockIdx.x;
    const float* x = in + row*(size_t)W;
    __half* y = out + row*(size_t)W;
    float s=0.f, s2=0.f;
    for (int i=threadIdx.x; i<W; i+=blockDim.x){ float v=x[i]; s+=v; s2+=v*v; }
    __shared__ float rs[32], rs2[32];
    int lane = threadIdx.x & 31, wid = threadIdx.x >> 5;
    #pragma unroll
    for (int o=16;o;o>>=1){ s += __shfl_xor_sync(0xffffffffu,s,o); s2 += __shfl_xor_sync(0xffffffffu,s2,o); }
    if (lane==0){ rs[wid]=s; rs2[wid]=s2; }
    __syncthreads();
    if (wid==0){
        float a  = (lane<8)? rs[lane]  : 0.f;
        float a2 = (lane<8)? rs2[lane] : 0.f;
        #pragma unroll
        for (int o=4;o;o>>=1){ a += __shfl_xor_sync(0xffffffffu,a,o); a2 += __shfl_xor_sync(0xffffffffu,a2,o); }
        if (lane==0){ rs[0]=a; rs2[0]=a2; }
    }
    __syncthreads();
    float mean = rs[0]/(float)W;
    float var  = rs2[0]/(float)W - mean*mean;
    float rstd = rsqrtf(var + 1e-5f);
    for (int i=threadIdx.x; i<W; i+=blockDim.x){
        float v = (x[i]-mean)*rstd*gamma[i] + beta[i];
        if (dosilu) v = silu_f(v);
        y[i] = __float2half(v);
    }
}

// ---------------- fused attention with in-kernel q/k layernorm; fp16 o --------------
// smem: gb[256], qs[65][64], vs[65][64], kt[64][68], S[65][68]
__global__ void __launch_bounds__(256)
attn_kernel(const float* __restrict__ qkv, const float* __restrict__ bias,
            __half* __restrict__ o,
            const float* __restrict__ qg, const float* __restrict__ qb,
            const float* __restrict__ kg, const float* __restrict__ kb)
{
    int bh = blockIdx.x;
    int b  = bh / NHEADS, hh = bh % NHEADS;
    extern __shared__ float sm[];
    float* gb = sm;                 // [4][64]: qg,qb,kg,kb
    float* qs = gb + 256;           // [65][64]
    float* vs = qs + NTOK*DHEAD;    // [65][64]
    float* kt = vs + NTOK*DHEAD;    // [64][68]
    float* S  = kt + DHEAD*68;      // [65][68]
    const int tid = threadIdx.x;

    {
        int a = tid>>6, i = tid&63;
        const float* src = (a==0)?qg:(a==1)?qb:(a==2)?kg:kb;
        gb[tid] = src[i];
    }
    __syncthreads();

    // load q,k,v; layernorm q and k rows in registers (16-lane groups per row)
    #pragma unroll
    for (int it=0; it<5; it++){
        int idx = tid + it*256;
        bool ok = idx < NTOK*16;
        int n = ok ? (idx>>4) : 0;
        int d4 = (idx&15)<<2;
        float4 q4 = make_float4(0,0,0,0), k4 = q4, v4 = q4;
        if (ok){
            const float* base = qkv + (size_t)(b*NTOK+n)*C3 + hh*DHEAD;
            q4 = *(const float4*)(base + d4);
            k4 = *(const float4*)(base + CDIM + d4);
            v4 = *(const float4*)(base + 2*CDIM + d4);
        }
        // q norm
        float s = q4.x + q4.y + q4.z + q4.w;
        #pragma unroll
        for (int off=8; off; off>>=1) s += __shfl_xor_sync(0xffffffffu, s, off);
        float mean = s*(1.f/64.f);
        float e0=q4.x-mean, e1=q4.y-mean, e2=q4.z-mean, e3=q4.w-mean;
        float ss = e0*e0 + e1*e1 + e2*e2 + e3*e3;
        #pragma unroll
        for (int off=8; off; off>>=1) ss += __shfl_xor_sync(0xffffffffu, ss, off);
        float rstd = rsqrtf(ss*(1.f/64.f) + 1e-5f);
        q4.x = (e0*rstd*gb[d4  ] + gb[64+d4  ])*0.125f;
        q4.y = (e1*rstd*gb[d4+1] + gb[64+d4+1])*0.125f;
        q4.z = (e2*rstd*gb[d4+2] + gb[64+d4+2])*0.125f;
        q4.w = (e3*rstd*gb[d4+3] + gb[64+d4+3])*0.125f;
        // k norm
        s = k4.x + k4.y + k4.z + k4.w;
        #pragma unroll
        for (int off=8; off; off>>=1) s += __shfl_xor_sync(0xffffffffu, s, off);
        mean = s*(1.f/64.f);
        e0=k4.x-mean; e1=k4.y-mean; e2=k4.z-mean; e3=k4.w-mean;
        ss = e0*e0 + e1*e1 + e2*e2 + e3*e3;
        #pragma unroll
        for (int off=8; off; off>>=1) ss += __shfl_xor_sync(0xffffffffu, ss, off);
        rstd = rsqrtf(ss*(1.f/64.f) + 1e-5f);
        k4.x = e0*rstd*gb[128+d4  ] + gb[192+d4  ];
        k4.y = e1*rstd*gb[128+d4+1] + gb[192+d4+1];
        k4.z = e2*rstd*gb[128+d4+2] + gb[192+d4+2];
        k4.w = e3*rstd*gb[128+d4+3] + gb[192+d4+3];
        if (ok){
            *(float4*)&qs[n*64 + d4] = q4;
            *(float4*)&vs[n*64 + d4] = v4;
            kt[(d4  )*68 + n] = k4.x;
            kt[(d4+1)*68 + n] = k4.y;
            kt[(d4+2)*68 + n] = k4.z;
            kt[(d4+3)*68 + n] = k4.w;
        }
    }
    __syncthreads();

    const float* bb = bias + (size_t)bh*BIASN;
    // S main tile 64x64, 16x16 threads x 4x4
    {
        const int it = tid>>4, jt = tid&15;
        const int i0 = it*4, j0 = jt*4;
        float acc[4][4];
        #pragma unroll
        for (int r=0;r<4;r++)
            #pragma unroll
            for (int c=0;c<4;c++)
                acc[r][c] = bb[(i0+r)*NTOK + j0 + c];
        #pragma unroll 8
        for (int d=0; d<DHEAD; d++){
            float4 kv = *(float4*)&kt[d*68 + j0];
            float q0 = qs[(i0+0)*64 + d];
            float q1 = qs[(i0+1)*64 + d];
            float q2 = qs[(i0+2)*64 + d];
            float q3 = qs[(i0+3)*64 + d];
            acc[0][0]+=q0*kv.x; acc[0][1]+=q0*kv.y; acc[0][2]+=q0*kv.z; acc[0][3]+=q0*kv.w;
            acc[1][0]+=q1*kv.x; acc[1][1]+=q1*kv.y; acc[1][2]+=q1*kv.z; acc[1][3]+=q1*kv.w;
            acc[2][0]+=q2*kv.x; acc[2][1]+=q2*kv.y; acc[2][2]+=q2*kv.z; acc[2][3]+=q2*kv.w;
            acc[3][0]+=q3*kv.x; acc[3][1]+=q3*kv.y; acc[3][2]+=q3*kv.z; acc[3][3]+=q3*kv.w;
        }
        #pragma unroll
        for (int r=0;r<4;r++)
            *(float4*)&S[(i0+r)*68 + j0] =
                make_float4(acc[r][0],acc[r][1],acc[r][2],acc[r][3]);
    }
    if (tid < 129){
        int i, j;
        if (tid < NTOK){ i = 64; j = tid; }
        else           { i = tid - NTOK; j = 64; }
        float a = bb[i*NTOK + j];
        #pragma unroll 16
        for (int d=0; d<DHEAD; d++) a += qs[i*64 + d] * kt[d*68 + j];
        S[i*68 + j] = a;
    }
    __syncthreads();

    // softmax
    {
        int wd = tid >> 5, lane = tid & 31;
        for (int i=wd; i<NTOK; i+=8){
            float* Sr = S + i*68;
            float m = -1e30f;
            for (int j=lane; j<NTOK; j+=32) m = fmaxf(m, Sr[j]);
            #pragma unroll
            for (int off=16;off;off>>=1) m = fmaxf(m, __shfl_xor_sync(0xffffffffu,m,off));
            float sum = 0.f;
            for (int j=lane; j<NTOK; j+=32){ float e = expf(Sr[j]-m); Sr[j]=e; sum+=e; }
            #pragma unroll
            for (int off=16;off;off>>=1) sum += __shfl_xor_sync(0xffffffffu,sum,off);
            float inv = 1.f/sum;
            for (int j=lane; j<NTOK; j+=32) Sr[j] *= inv;
        }
    }
    __syncthreads();

    // O = P @ V
    {
        const int it = tid>>4, dt = tid&15;
        const int i0 = it*4, d0 = dt*4;
        float acc[4][4];
        #pragma unroll
        for (int r=0;r<4;r++)
            #pragma unroll
            for (int c=0;c<4;c++) acc[r][c]=0.f;
        #pragma unroll 5
        for (int j=0; j<NTOK; j++){
            float4 vv = *(float4*)&vs[j*64 + d0];
            float s0 = S[(i0+0)*68 + j];
            float s1 = S[(i0+1)*68 + j];
            float s2 = S[(i0+2)*68 + j];
            float s3 = S[(i0+3)*68 + j];
            acc[0][0]+=s0*vv.x; acc[0][1]+=s0*vv.y; acc[0][2]+=s0*vv.z; acc[0][3]+=s0*vv.w;
            acc[1][0]+=s1*vv.x; acc[1][1]+=s1*vv.y; acc[1][2]+=s1*vv.z; acc[1][3]+=s1*vv.w;
            acc[2][0]+=s2*vv.x; acc[2][1]+=s2*vv.y; acc[2][2]+=s2*vv.z; acc[2][3]+=s2*vv.w;
            acc[3][0]+=s3*vv.x; acc[3][1]+=s3*vv.y; acc[3][2]+=s3*vv.z; acc[3][3]+=s3*vv.w;
        }
        #pragma unroll
        for (int r=0;r<4;r++){
            __half2 h0 = __floats2half2_rn(acc[r][0], acc[r][1]);
            __half2 h1 = __floats2half2_rn(acc[r][2], acc[r][3]);
            __half* op = o + (size_t)(b*NTOK + i0 + r)*CDIM + hh*DHEAD + d0;
            *(__half2*)(op)   = h0;
            *(__half2*)(op+2) = h1;
        }
    }
    if (tid < DHEAD){
        int d = tid;
        float a = 0.f;
        #pragma unroll 5
        for (int j=0; j<NTOK; j++) a += S[64*68 + j] * vs[j*64 + d];
        o[(size_t)(b*NTOK + 64)*CDIM + hh*DHEAD + d] = __float2half(a);
    }
}

// ---------------- weight transpose: fp32 in[K][N] -> fp16 out[Npad][K] --------------
__global__ void transpose_pad_h(const float* __restrict__ in, __half* __restrict__ out,
                                int K, int N, int Npad)
{
    __shared__ float t[32][33];
    int kb = blockIdx.y*32, nb = blockIdx.x*32;
    #pragma unroll
    for (int i=0;i<4;i++){
        int k = kb + threadIdx.y + i*8, n = nb + threadIdx.x;
        t[threadIdx.y+i*8][threadIdx.x] = (k<K && n<N) ? in[(size_t)k*N + n] : 0.f;
    }
    __syncthreads();
    #pragma unroll
    for (int i=0;i<4;i++){
        int n = nb + threadIdx.y + i*8, k = kb + threadIdx.x;
        if (n<Npad && k<K) out[(size_t)n*K + k] = __float2half(t[threadIdx.x][threadIdx.y+i*8]);
    }
}

// ---------------- host ----------------
static inline void tlaunch(const float* in, __half* out, int K, int N, int Npad,
                           cudaStream_t st){
    transpose_pad_h<<<dim3((Npad+31)/32,(K+31)/32), dim3(32,8), 0, st>>>(in, out, K, N, Npad);
}

extern "C" void kernel_launch(void* const* d_in, const int* in_sizes, int n_in,
                              void* d_out, int out_size)
{
    (void)in_sizes; (void)n_in; (void)out_size;
    const float* ln1_g  = (const float*)d_in[1];
    const float* ln1_b  = (const float*)d_in[2];
    const float* qkv_w  = (const float*)d_in[3];
    const float* proj_w = (const float*)d_in[4];
    const float* qn_g   = (const float*)d_in[5];
    const float* qn_b   = (const float*)d_in[6];
    const float* kn_g   = (const float*)d_in[7];
    const float* kn_b   = (const float*)d_in[8];
    const float* sg_w1  = (const float*)d_in[9];
    const float* sg1g   = (const float*)d_in[10];
    const float* sg1b   = (const float*)d_in[11];
    const float* sg_w2  = (const float*)d_in[12];
    const float* sg2g   = (const float*)d_in[13];
    const float* sg2b   = (const float*)d_in[14];
    const float* bw     = (const float*)d_in[15];
    const float* ln2_g  = (const float*)d_in[16];
    const float* ln2_b  = (const float*)d_in[17];
    const float* gate_w = (const float*)d_in[18];
    const float* value_w= (const float*)d_in[19];
    const float* out_w  = (const float*)d_in[20];

    float* X = (float*)d_out;

    void *ph,*pqkv,*po,*pgated,*pbias,*psg1,*psg1h,*psg2,*psg2h;
    void *ptqkv,*ptproj,*ptgate,*ptval,*ptout,*ptsg1,*ptsg2,*ptbw;
    cudaGetSymbolAddress(&ph,g_h); cudaGetSymbolAddress(&pqkv,g_qkv);
    cudaGetSymbolAddress(&po,g_o); cudaGetSymbolAddress(&pgated,g_gated);
    cudaGetSymbolAddress(&pbias,g_bias);
    cudaGetSymbolAddress(&psg1,g_sg1); cudaGetSymbolAddress(&psg1h,g_sg1h);
    cudaGetSymbolAddress(&psg2,g_sg2); cudaGetSymbolAddress(&psg2h,g_sg2h);
    cudaGetSymbolAddress(&ptqkv,g_tqkv); cudaGetSymbolAddress(&ptproj,g_tproj);
    cudaGetSymbolAddress(&ptgate,g_tgate); cudaGetSymbolAddress(&ptval,g_tval);
    cudaGetSymbolAddress(&ptout,g_tout); cudaGetSymbolAddress(&ptsg1,g_tsg1);
    cudaGetSymbolAddress(&ptsg2,g_tsg2); cudaGetSymbolAddress(&ptbw,g_tbw);
    __half* h=(__half*)ph; float* qkv=(float*)pqkv; __half* o=(__half*)po;
    __half* gated=(__half*)pgated; float* bias=(float*)pbias;
    float* sg1=(float*)psg1; __half* sg1h=(__half*)psg1h;
    float* sg2=(float*)psg2; __half* sg2h=(__half*)psg2h;

    auto buf = [](void* base, int p, size_t n)->__half*{ return (__half*)base + (size_t)p*n; };

    // streams / events created once (first call is the uncaptured correctness run)
    static cudaStream_t s_sg = 0;
    static cudaEvent_t e_h[NUM_LAYERS], e_b[NUM_LAYERS], e_t[NUM_LAYERS+1];
    if (!s_sg){
        cudaStreamCreateWithFlags(&s_sg, cudaStreamNonBlocking);
        for (int l=0;l<NUM_LAYERS;l++){
            cudaEventCreateWithFlags(&e_h[l], cudaEventDisableTiming);
            cudaEventCreateWithFlags(&e_b[l], cudaEventDisableTiming);
            cudaEventCreateWithFlags(&e_t[l+1], cudaEventDisableTiming);
        }
    }

    const int attn_smem = (256 + NTOK*DHEAD + NTOK*DHEAD + DHEAD*68 + NTOK*68) * 4;
    cudaFuncSetAttribute(attn_kernel, cudaFuncAttributeMaxDynamicSharedMemorySize, attn_smem);
    const int g_smem = 2*NSTAGE*ASTG;
    const int d_smem = NSTAGE*ASTG + 2*NSTAGE*64*SROW;
    cudaFuncSetAttribute(gemm_h<0,false>, cudaFuncAttributeMaxDynamicSharedMemorySize, g_smem);
    cudaFuncSetAttribute(gemm_h<1,false>, cudaFuncAttributeMaxDynamicSharedMemorySize, g_smem);
    cudaFuncSetAttribute(gemm_h<0,true>,  cudaFuncAttributeMaxDynamicSharedMemorySize, g_smem);
    cudaFuncSetAttribute(gemm_dual_h,     cudaFuncAttributeMaxDynamicSharedMemorySize, d_smem);

    cudaMemcpyAsync(X, d_in[0], sizeof(float)*(size_t)ROWS*CDIM, cudaMemcpyDeviceToDevice);

    // layer-0 transposes on main stream
    {
        tlaunch(qkv_w,   buf(ptqkv,0,(size_t)C3*CDIM),  CDIM, C3,   C3,   0);
        tlaunch(proj_w,  buf(ptproj,0,(size_t)CDIM*CDIM),CDIM, CDIM, CDIM, 0);
        tlaunch(gate_w,  buf(ptgate,0,(size_t)C4*CDIM), CDIM, C4,   C4,   0);
        tlaunch(value_w, buf(ptval,0,(size_t)C4*CDIM),  CDIM, C4,   C4,   0);
        tlaunch(out_w,   buf(ptout,0,(size_t)CDIM*C4),  C4,   CDIM, CDIM, 0);
        tlaunch(sg_w1,   buf(ptsg1,0,(size_t)512*CDIM), CDIM, 512,  512,  0);
        tlaunch(sg_w2,   buf(ptsg2,0,(size_t)3072*512), 512,  3072, 3072, 0);
        tlaunch(bw,      buf(ptbw,0,(size_t)BIASNP*LATD),LATD, BIASN, BIASNP, 0);
    }

    for (int l=0; l<NUM_LAYERS; l++){
        const int p = l & 1;
        __half* tqkv = buf(ptqkv,p,(size_t)C3*CDIM);
        __half* tproj= buf(ptproj,p,(size_t)CDIM*CDIM);
        __half* tgate= buf(ptgate,p,(size_t)C4*CDIM);
        __half* tval = buf(ptval,p,(size_t)C4*CDIM);
        __half* tout = buf(ptout,p,(size_t)CDIM*C4);
        __half* tsg1 = buf(ptsg1,p,(size_t)512*CDIM);
        __half* tsg2 = buf(ptsg2,p,(size_t)3072*512);
        __half* tbw  = buf(ptbw,p,(size_t)BIASNP*LATD);

        // h = LN1(x)
        ln_h_kernel<<<ROWS,256>>>(X, h, ln1_g+(size_t)l*CDIM, ln1_b+(size_t)l*CDIM, CDIM, 0);
        cudaEventRecord(e_h[l], 0);
        cudaStreamWaitEvent(s_sg, e_h[l], 0);

        // side stream: structure-gate bias chain
        gemm_h<0,false><<<dim3(4,4), 256, g_smem, s_sg>>>(
            h, tsg1, sg1, 512, 512, CDIM, NTOK*CDIM, 512);
        ln_h_kernel<<<512,256,0,s_sg>>>(sg1, sg1h, sg1g+(size_t)l*512, sg1b+(size_t)l*512, 512, 1);
        gemm_h<0,false><<<dim3(24,4), 256, g_smem, s_sg>>>(
            sg1h, tsg2, sg2, 512, 3072, 512, 512, 3072);
        ln_h_kernel<<<512,256,0,s_sg>>>(sg2, sg2h, sg2g+(size_t)l*3072, sg2b+(size_t)l*3072, 3072, 0);
        gemm_h<0,true><<<dim3(BIASNP/128, BHD/128), 256, g_smem, s_sg>>>(
            sg2h, tbw, bias, BHD, BIASN, LATD, LATD, BIASN);
        cudaEventRecord(e_b[l], s_sg);

        // side stream: prefetch next-layer transposes (parity p^1)
        if (l+1 < NUM_LAYERS){
            const int q = (l+1)&1;
            tlaunch(qkv_w  + (size_t)(l+1)*CDIM*C3,   buf(ptqkv,q,(size_t)C3*CDIM),  CDIM, C3,   C3,   s_sg);
            tlaunch(proj_w + (size_t)(l+1)*CDIM*CDIM, buf(ptproj,q,(size_t)CDIM*CDIM),CDIM, CDIM, CDIM, s_sg);
            tlaunch(gate_w + (size_t)(l+1)*CDIM*C4,   buf(ptgate,q,(size_t)C4*CDIM), CDIM, C4,   C4,   s_sg);
            tlaunch(value_w+ (size_t)(l+1)*CDIM*C4,   buf(ptval,q,(size_t)C4*CDIM),  CDIM, C4,   C4,   s_sg);
            tlaunch(out_w  + (size_t)(l+1)*C4*CDIM,   buf(ptout,q,(size_t)CDIM*C4),  C4,   CDIM, CDIM, s_sg);
            tlaunch(sg_w1  + (size_t)(l+1)*CDIM*512,  buf(ptsg1,q,(size_t)512*CDIM), CDIM, 512,  512,  s_sg);
            tlaunch(sg_w2  + (size_t)(l+1)*512*3072,  buf(ptsg2,q,(size_t)3072*512), 512,  3072, 3072, s_sg);
            tlaunch(bw     + (size_t)(l+1)*LATD*BIASN,buf(ptbw,q,(size_t)BIASNP*LATD),LATD, BIASN, BIASNP, s_sg);
            cudaEventRecord(e_t[l+1], s_sg);
        }

        // main stream: qkv GEMM (overlaps side chain)
        gemm_h<0,false><<<dim3(C3/128, ROWS/128), 256, g_smem>>>(
            h, tqkv, qkv, ROWS, C3, CDIM, CDIM, C3);

        // join side chain, then attention (with fused q/k layernorm)
        cudaStreamWaitEvent(0, e_b[l], 0);
        attn_kernel<<<BHD, 256, attn_smem>>>(qkv, bias, o,
            qn_g+(size_t)l*DHEAD, qn_b+(size_t)l*DHEAD,
            kn_g+(size_t)l*DHEAD, kn_b+(size_t)l*DHEAD);
        // x += o @ proj_w
        gemm_h<1,false><<<dim3(CDIM/128, ROWS/128), 256, g_smem>>>(
            o, tproj, X, ROWS, CDIM, CDIM, CDIM, CDIM);
        // h2 = LN2(x)
        ln_h_kernel<<<ROWS,256>>>(X, h, ln2_g+(size_t)l*CDIM, ln2_b+(size_t)l*CDIM, CDIM, 0);
        // gated = (h2@gate_w) * silu(h2@value_w)
        gemm_dual_h<<<dim3(C4/64, ROWS/128), 256, d_smem>>>(
            h, tgate, tval, gated, ROWS, C4, CDIM, CDIM, C4);
        // x += gated @ out_w
        gemm_h<1,false><<<dim3(CDIM/128, ROWS/128), 256, g_smem>>>(
            gated, tout, X, ROWS, CDIM, C4, C4, CDIM);

        // next-layer transposed weights must be ready before next qkv GEMM
        if (l+1 < NUM_LAYERS) cudaStreamWaitEvent(0, e_t[l+1], 0);
    }
}

// round 15
// speedup vs baseline: 3.1534x; 1.0403x over previous
#include <cuda_runtime.h>
#include <cuda_fp16.h>
#include <math.h>
#include <stdint.h>

#define NUM_LAYERS 6
#define CDIM 768
#define NHEADS 12
#define DHEAD 64
#define LATD 256
#define NTOK 65
#define BATCH 512
#define ROWS (BATCH*NTOK)          // 33280
#define C3 (3*CDIM)                // 2304
#define C4 (4*CDIM)                // 3072
#define BHD (BATCH*NHEADS)         // 6144
#define BIASN (NTOK*NTOK)          // 4225
#define BIASNP 4352                // padded to %128

// ---------------- scratch (static device allocations; no cudaMalloc) ----------------
__device__ __align__(256) __half g_h    [(size_t)ROWS*CDIM];
__device__ __align__(256) __half g_qkvh [(size_t)ROWS*C3];     // qkv fp16
__device__ __align__(256) __half g_o    [(size_t)ROWS*CDIM];
__device__ __align__(256) __half g_gated[(size_t)ROWS*C4];
__device__ __align__(256) float  g_bias [(size_t)BHD*BIASN];
__device__ __align__(256) float  g_sg1  [512*512];
__device__ __align__(256) __half g_sg1h [512*512];
__device__ __align__(256) float  g_sg2  [512*3072];
__device__ __align__(256) __half g_sg2h [512*3072];
// double-buffered transposed (K-major, [N][K]) fp16 weights
__device__ __align__(256) __half g_tqkv [2][C3*CDIM];
__device__ __align__(256) __half g_tproj[2][CDIM*CDIM];
__device__ __align__(256) __half g_tgate[2][C4*CDIM];
__device__ __align__(256) __half g_tval [2][C4*CDIM];
__device__ __align__(256) __half g_tout [2][CDIM*C4];
__device__ __align__(256) __half g_tsg1 [2][512*CDIM];
__device__ __align__(256) __half g_tsg2 [2][3072*512];
__device__ __align__(256) __half g_tbw  [2][(size_t)BIASNP*LATD];

// ---------------- PTX helpers ----------------
__device__ __forceinline__ uint32_t smem_u32(const void* p){
    uint32_t a;
    asm("{ .reg .u64 t; cvta.to.shared.u64 t, %1; cvt.u32.u64 %0, t; }" : "=r"(a) : "l"(p));
    return a;
}
__device__ __forceinline__ void cpa16(uint32_t s, const void* g){
    asm volatile("cp.async.cg.shared.global [%0], [%1], 16;" :: "r"(s), "l"(g));
}
#define CP_COMMIT() asm volatile("cp.async.commit_group;")
#define CP_WAIT2()  asm volatile("cp.async.wait_group 2;")
__device__ __forceinline__ void ldsm4(uint32_t* r, uint32_t addr){
    asm volatile("ldmatrix.sync.aligned.m8n8.x4.shared.b16 {%0,%1,%2,%3}, [%4];"
        : "=r"(r[0]),"=r"(r[1]),"=r"(r[2]),"=r"(r[3]) : "r"(addr));
}
__device__ __forceinline__ void mma16816(float* c, const uint32_t* a, uint32_t b0, uint32_t b1){
    asm volatile(
      "mma.sync.aligned.m16n8k16.row.col.f32.f16.f16.f32 "
      "{%0,%1,%2,%3},{%4,%5,%6,%7},{%8,%9},{%0,%1,%2,%3};"
      : "+f"(c[0]),"+f"(c[1]),"+f"(c[2]),"+f"(c[3])
      : "r"(a[0]),"r"(a[1]),"r"(a[2]),"r"(a[3]),"r"(b0),"r"(b1));
}
__device__ __forceinline__ float silu_f(float v){ return v/(1.f+expf(-v)); }

#define SROW   80
#define ASTG   (128*SROW)
#define NSTAGE 4

// =====================================================================================
// fp16 GEMM: C[M,N] = A[M,K](fp16) @ Bt[N][K](fp16)^T.
// EPI: 0 store, 1 residual add (fp32 C). HOUT: fp16 C (EPI=0 only). NGUARD: col guard.
// =====================================================================================
template<int EPI, bool NGUARD, bool HOUT>
__global__ void __launch_bounds__(256,2)
gemm_h(const __half* __restrict__ A, const __half* __restrict__ Bt,
       void* __restrict__ Cv, int M, int N, int K, int lda, int ldc)
{
    extern __shared__ __align__(128) char dyn[];
    const uint32_t sA = smem_u32(dyn);
    const uint32_t sB = sA + NSTAGE*ASTG;

    const int tid = threadIdx.x, wid = tid>>5, lane = tid&31;
    const int wm = wid>>2, wn = wid&3;
    const size_t bm = (size_t)blockIdx.y*128;
    const size_t bn = (size_t)blockIdx.x*128;
    const int KT = K/32;

    float acc[4][4][4];
    #pragma unroll
    for (int i=0;i<4;i++) for (int j=0;j<4;j++) for (int r=0;r<4;r++) acc[i][j][r]=0.f;

    auto LOADS = [&](int s, int t){
        const uint32_t sa = sA + s*ASTG, sb = sB + s*ASTG;
        #pragma unroll
        for (int u=0;u<2;u++){
            int c = tid + u*256;
            int row = c>>2, col8 = (c&3)*8;
            cpa16(sa + row*SROW + col8*2, A  + (bm+row)*(size_t)lda + (size_t)t*32 + col8);
            cpa16(sb + row*SROW + col8*2, Bt + (bn+row)*(size_t)K   + (size_t)t*32 + col8);
        }
    };
    auto COMPUTE = [&](int s){
        const uint32_t sa = sA + s*ASTG, sb = sB + s*ASTG;
        #pragma unroll
        for (int kc=0;kc<2;kc++){
            uint32_t af[4][4], bf[2][4];
            #pragma unroll
            for (int i=0;i<4;i++){
                int r = wm*64 + i*16 + (lane&7) + ((lane>>3)&1)*8;
                int k = kc*16 + (lane>>4)*8;
                ldsm4(af[i], sa + r*SROW + k*2);
            }
            #pragma unroll
            for (int jj=0;jj<2;jj++){
                int n = wn*32 + jj*16 + ((lane>>4)<<3) + (lane&7);
                int k = kc*16 + ((lane>>3)&1)*8;
                ldsm4(bf[jj], sb + n*SROW + k*2);
            }
            #pragma unroll
            for (int i=0;i<4;i++)
              #pragma unroll
              for (int jj=0;jj<2;jj++){
                mma16816(acc[i][jj*2  ], af[i], bf[jj][0], bf[jj][1]);
                mma16816(acc[i][jj*2+1], af[i], bf[jj][2], bf[jj][3]);
              }
        }
    };

    LOADS(0,0); CP_COMMIT();
    if (KT>1) LOADS(1,1);
    CP_COMMIT();
    if (KT>2) LOADS(2,2);
    CP_COMMIT();
    for (int t=0;t<KT;t++){
        CP_WAIT2();
        __syncthreads();
        COMPUTE(t%NSTAGE);
        int nt = t+3;
        if (nt<KT) LOADS(nt%NSTAGE, nt);
        CP_COMMIT();
    }

    const int r4 = lane>>2, c2 = (lane&3)*2;
    #pragma unroll
    for (int i=0;i<4;i++){
        size_t r0 = bm + wm*64 + i*16 + r4;
        #pragma unroll
        for (int j=0;j<4;j++){
            size_t col = bn + wn*32 + j*8 + c2;
            if (HOUT){
                __half* Cp0 = (__half*)Cv + r0*(size_t)ldc;
                __half* Cp1 = Cp0 + 8*(size_t)ldc;
                *(__half2*)(Cp0+col) = __floats2half2_rn(acc[i][j][0], acc[i][j][1]);
                *(__half2*)(Cp1+col) = __floats2half2_rn(acc[i][j][2], acc[i][j][3]);
            } else {
                float* Cp0 = (float*)Cv + r0*(size_t)ldc;
                float* Cp1 = Cp0 + 8*(size_t)ldc;
                if (!NGUARD){
                    float2* p0 = (float2*)(Cp0+col);
                    float2* p1 = (float2*)(Cp1+col);
                    float2 v0 = make_float2(acc[i][j][0], acc[i][j][1]);
                    float2 v1 = make_float2(acc[i][j][2], acc[i][j][3]);
                    if (EPI==1){ float2 o0=*p0, o1=*p1; v0.x+=o0.x; v0.y+=o0.y; v1.x+=o1.x; v1.y+=o1.y; }
                    *p0 = v0; *p1 = v1;
                } else {
                    if ((long long)col < N){
                        float v = acc[i][j][0]; if (EPI==1) v += Cp0[col]; Cp0[col]=v;
                        v = acc[i][j][2]; if (EPI==1) v += Cp1[col]; Cp1[col]=v;
                    }
                    if ((long long)col+1 < N){
                        float v = acc[i][j][1]; if (EPI==1) v += Cp0[col+1]; Cp0[col+1]=v;
                        v = acc[i][j][3]; if (EPI==1) v += Cp1[col+1]; Cp1[col+1]=v;
                    }
                }
            }
        }
    }
}

// =====================================================================================
// dual fp16 GEMM: C(fp16) = (A@G^T) * silu(A@V^T). Tile 128x64x32.
// =====================================================================================
__global__ void __launch_bounds__(256,2)
gemm_dual_h(const __half* __restrict__ A, const __half* __restrict__ Gt,
            const __half* __restrict__ Vt, __half* __restrict__ C,
            int M, int N, int K, int lda, int ldc)
{
    extern __shared__ __align__(128) char dyn[];
    const uint32_t sA = smem_u32(dyn);
    const uint32_t sG = sA + NSTAGE*ASTG;
    const uint32_t sV = sG + NSTAGE*(64*SROW);

    const int tid = threadIdx.x, wid = tid>>5, lane = tid&31;
    const int wm = wid>>2, wn = wid&3;
    const size_t bm = (size_t)blockIdx.y*128;
    const size_t bn = (size_t)blockIdx.x*64;
    const int KT = K/32;

    float ag[4][2][4], av[4][2][4];
    #pragma unroll
    for (int i=0;i<4;i++) for (int j=0;j<2;j++) for (int r=0;r<4;r++){ ag[i][j][r]=0.f; av[i][j][r]=0.f; }

    auto LOADS = [&](int s, int t){
        const uint32_t sa = sA + s*ASTG;
        const uint32_t sg = sG + s*(64*SROW);
        const uint32_t sv = sV + s*(64*SROW);
        #pragma unroll
        for (int u=0;u<2;u++){
            int c = tid + u*256;
            int row = c>>2, col8 = (c&3)*8;
            cpa16(sa + row*SROW + col8*2, A + (bm+row)*(size_t)lda + (size_t)t*32 + col8);
        }
        {
            int row = tid>>2, col8 = (tid&3)*8;
            cpa16(sg + row*SROW + col8*2, Gt + (bn+row)*(size_t)K + (size_t)t*32 + col8);
            cpa16(sv + row*SROW + col8*2, Vt + (bn+row)*(size_t)K + (size_t)t*32 + col8);
        }
    };
    auto COMPUTE = [&](int s){
        const uint32_t sa = sA + s*ASTG;
        const uint32_t sg = sG + s*(64*SROW);
        const uint32_t sv = sV + s*(64*SROW);
        #pragma unroll
        for (int kc=0;kc<2;kc++){
            uint32_t af[4][4], gf[4], vf[4];
            #pragma unroll
            for (int i=0;i<4;i++){
                int r = wm*64 + i*16 + (lane&7) + ((lane>>3)&1)*8;
                int k = kc*16 + (lane>>4)*8;
                ldsm4(af[i], sa + r*SROW + k*2);
            }
            {
                int n = wn*16 + ((lane>>4)<<3) + (lane&7);
                int k = kc*16 + ((lane>>3)&1)*8;
                ldsm4(gf, sg + n*SROW + k*2);
                ldsm4(vf, sv + n*SROW + k*2);
            }
            #pragma unroll
            for (int i=0;i<4;i++){
                mma16816(ag[i][0], af[i], gf[0], gf[1]);
                mma16816(ag[i][1], af[i], gf[2], gf[3]);
                mma16816(av[i][0], af[i], vf[0], vf[1]);
                mma16816(av[i][1], af[i], vf[2], vf[3]);
            }
        }
    };

    LOADS(0,0); CP_COMMIT();
    if (KT>1) LOADS(1,1);
    CP_COMMIT();
    if (KT>2) LOADS(2,2);
    CP_COMMIT();
    for (int t=0;t<KT;t++){
        CP_WAIT2();
        __syncthreads();
        COMPUTE(t%NSTAGE);
        int nt = t+3;
        if (nt<KT) LOADS(nt%NSTAGE, nt);
        CP_COMMIT();
    }

    const int r4 = lane>>2, c2 = (lane&3)*2;
    #pragma unroll
    for (int i=0;i<4;i++){
        size_t r0 = bm + wm*64 + i*16 + r4;
        __half* Cp0 = C + r0*(size_t)ldc;
        __half* Cp1 = Cp0 + 8*(size_t)ldc;
        #pragma unroll
        for (int j=0;j<2;j++){
            size_t col = bn + wn*16 + j*8 + c2;
            __half2 v0 = __floats2half2_rn(ag[i][j][0]*silu_f(av[i][j][0]),
                                           ag[i][j][1]*silu_f(av[i][j][1]));
            __half2 v1 = __floats2half2_rn(ag[i][j][2]*silu_f(av[i][j][2]),
                                           ag[i][j][3]*silu_f(av[i][j][3]));
            *(__half2*)(Cp0+col) = v0;
            *(__half2*)(Cp1+col) = v1;
        }
    }
}

// ---------------- LayerNorm (fp32 in, fp16 out; optional silu) ----------------
__global__ void ln_h_kernel(const float* __restrict__ in, __half* __restrict__ out,
                            const float* __restrict__ gamma, const float* __restrict__ beta,
                            int W, int dosilu)
{
    size_t row = blockIdx.x;
    const float* x = in + row*(size_t)W;
    __half* y = out + row*(size_t)W;
    float s=0.f, s2=0.f;
    for (int i=threadIdx.x; i<W; i+=blockDim.x){ float v=x[i]; s+=v; s2+=v*v; }
    __shared__ float rs[32], rs2[32];
    int lane = threadIdx.x & 31, wid = threadIdx.x >> 5;
    #pragma unroll
    for (int o=16;o;o>>=1){ s += __shfl_xor_sync(0xffffffffu,s,o); s2 += __shfl_xor_sync(0xffffffffu,s2,o); }
    if (lane==0){ rs[wid]=s; rs2[wid]=s2; }
    __syncthreads();
    if (wid==0){
        float a  = (lane<8)? rs[lane]  : 0.f;
        float a2 = (lane<8)? rs2[lane] : 0.f;
        #pragma unroll
        for (int o=4;o;o>>=1){ a += __shfl_xor_sync(0xffffffffu,a,o); a2 += __shfl_xor_sync(0xffffffffu,a2,o); }
        if (lane==0){ rs[0]=a; rs2[0]=a2; }
    }
    __syncthreads();
    float mean = rs[0]/(float)W;
    float var  = rs2[0]/(float)W - mean*mean;
    float rstd = rsqrtf(var + 1e-5f);
    for (int i=threadIdx.x; i<W; i+=blockDim.x){
        float v = (x[i]-mean)*rstd*gamma[i] + beta[i];
        if (dosilu) v = silu_f(v);
        y[i] = __float2half(v);
    }
}

// =====================================================================================
// tensorized attention per (b,h): qk-LN fused; S=QK^T+bias (mma), softmax, O=PV (mma)
// smem: gb[256]f, qh[80][72]h, kh[80][72]h, vt[64][88]h, Sf[80][84]f, Ph[80][88]h
// =====================================================================================
#define QKS 72
#define VTS 88
#define SFS 84
#define PHS 88
__global__ void __launch_bounds__(256)
attn_kernel(const __half* __restrict__ qkv, const float* __restrict__ bias,
            __half* __restrict__ o,
            const float* __restrict__ qg, const float* __restrict__ qb,
            const float* __restrict__ kg, const float* __restrict__ kb)
{
    int bh = blockIdx.x;
    int b  = bh / NHEADS, hh = bh % NHEADS;
    extern __shared__ __align__(16) char smraw[];
    float*  gb = (float*)smraw;                      // 1024 B
    __half* qh = (__half*)(smraw + 1024);            // 80*72*2 = 11520
    __half* kh = (__half*)(smraw + 1024 + 11520);    // 11520
    __half* vt = (__half*)(smraw + 1024 + 23040);    // 64*88*2 = 11264
    float*  Sf = (float*)(smraw + 1024 + 34304);     // 80*84*4 = 26880
    __half* Ph = (__half*)(smraw + 1024 + 61184);    // 80*88*2 = 14080
    const uint32_t qh_a = smem_u32(qh);
    const uint32_t kh_a = smem_u32(kh);
    const uint32_t vt_a = smem_u32(vt);
    const uint32_t ph_a = smem_u32(Ph);
    const int tid = threadIdx.x, wid = tid>>5, lane = tid&31;

    {
        int a = tid>>6, i = tid&63;
        const float* src = (a==0)?qg:(a==1)?qb:(a==2)?kg:kb;
        gb[tid] = src[i];
    }
    // zero vt pad cols j=65..79, Ph pad rows 65..79
    for (int idx=tid; idx<64*15; idx+=256){
        int d = idx/15, j = 65 + idx%15;
        vt[d*VTS + j] = __float2half(0.f);
    }
    for (int idx=tid; idx<15*80; idx+=256){
        Ph[(65+idx/80)*PHS + (idx%80)] = __float2half(0.f);
    }
    __syncthreads();

    // load + fused q/k layernorm (8 threads per row, 8 halves each)
    #pragma unroll
    for (int kit=0; kit<3; kit++){
        int idx = tid + kit*256;
        bool ok = idx < NTOK*8;
        int n = ok ? (idx>>3) : 0;
        int c8 = (idx&7)*8;
        float qf[8], kf[8]; __half vh[8];
        if (ok){
            const __half* base = qkv + (size_t)(b*NTOK+n)*C3 + hh*DHEAD;
            uint4 qv = *(const uint4*)(base + c8);
            uint4 kv = *(const uint4*)(base + CDIM + c8);
            uint4 vv = *(const uint4*)(base + 2*CDIM + c8);
            const __half* qp = (const __half*)&qv;
            const __half* kp = (const __half*)&kv;
            const __half* vp = (const __half*)&vv;
            #pragma unroll
            for (int i=0;i<8;i++){ qf[i]=__half2float(qp[i]); kf[i]=__half2float(kp[i]); vh[i]=vp[i]; }
        } else {
            #pragma unroll
            for (int i=0;i<8;i++){ qf[i]=0.f; kf[i]=0.f; vh[i]=__float2half(0.f); }
        }
        // q norm (groups of 8 lanes)
        float s = 0.f;
        #pragma unroll
        for (int i=0;i<8;i++) s += qf[i];
        #pragma unroll
        for (int off=4; off; off>>=1) s += __shfl_xor_sync(0xffffffffu, s, off);
        float mean = s*(1.f/64.f);
        float ss = 0.f;
        #pragma unroll
        for (int i=0;i<8;i++){ qf[i]-=mean; ss += qf[i]*qf[i]; }
        #pragma unroll
        for (int off=4; off; off>>=1) ss += __shfl_xor_sync(0xffffffffu, ss, off);
        float rstd = rsqrtf(ss*(1.f/64.f) + 1e-5f);
        #pragma unroll
        for (int i=0;i<8;i++) qf[i] = (qf[i]*rstd*gb[c8+i] + gb[64+c8+i])*0.125f;
        // k norm
        s = 0.f;
        #pragma unroll
        for (int i=0;i<8;i++) s += kf[i];
        #pragma unroll
        for (int off=4; off; off>>=1) s += __shfl_xor_sync(0xffffffffu, s, off);
        mean = s*(1.f/64.f);
        ss = 0.f;
        #pragma unroll
        for (int i=0;i<8;i++){ kf[i]-=mean; ss += kf[i]*kf[i]; }
        #pragma unroll
        for (int off=4; off; off>>=1) ss += __shfl_xor_sync(0xffffffffu, ss, off);
        rstd = rsqrtf(ss*(1.f/64.f) + 1e-5f);
        #pragma unroll
        for (int i=0;i<8;i++) kf[i] = kf[i]*rstd*gb[128+c8+i] + gb[192+c8+i];
        if (ok){
            __half2 qo[4], ko[4];
            #pragma unroll
            for (int i=0;i<4;i++){
                qo[i] = __floats2half2_rn(qf[2*i], qf[2*i+1]);
                ko[i] = __floats2half2_rn(kf[2*i], kf[2*i+1]);
            }
            *(uint4*)&qh[n*QKS + c8] = *(uint4*)qo;
            *(uint4*)&kh[n*QKS + c8] = *(uint4*)ko;
            #pragma unroll
            for (int i=0;i<8;i++) vt[(c8+i)*VTS + n] = vh[i];
        }
    }
    __syncthreads();

    const float* bb = bias + (size_t)bh*BIASN;
    const int fr = lane>>2, fc = (lane&3)*2;

    // S = QK^T + bias : 25 units of m16 x n16, K=64
    for (int u = wid; u < 25; u += 8){
        int m0 = (u/5)*16, n0 = (u%5)*16;
        float acc[2][4];
        #pragma unroll
        for (int jj=0;jj<2;jj++){
            int col = n0 + jj*8 + fc;
            #pragma unroll
            for (int r=0;r<4;r++){
                int row = m0 + fr + ((r>=2)?8:0);
                int c = col + (r&1);
                acc[jj][r] = (row<NTOK && c<NTOK) ? bb[row*NTOK + c] : 0.f;
            }
        }
        #pragma unroll
        for (int kt=0;kt<4;kt++){
            uint32_t a[4], bf[4];
            int ar = m0 + (lane&7) + ((lane>>3)&1)*8;
            int ak = kt*16 + (lane>>4)*8;
            ldsm4(a, qh_a + ar*(QKS*2) + ak*2);
            int bn_ = n0 + ((lane>>4)<<3) + (lane&7);
            int bk = kt*16 + ((lane>>3)&1)*8;
            ldsm4(bf, kh_a + bn_*(QKS*2) + bk*2);
            mma16816(acc[0], a, bf[0], bf[1]);
            mma16816(acc[1], a, bf[2], bf[3]);
        }
        #pragma unroll
        for (int jj=0;jj<2;jj++){
            int col = n0 + jj*8 + fc;
            *(float2*)&Sf[(m0+fr)*SFS + col]   = make_float2(acc[jj][0], acc[jj][1]);
            *(float2*)&Sf[(m0+fr+8)*SFS + col] = make_float2(acc[jj][2], acc[jj][3]);
        }
    }
    __syncthreads();

    // softmax rows < 65 ; write P fp16 (pad cols 65..79 zero)
    for (int i = wid; i < NTOK; i += 8){
        float* Sr = Sf + i*SFS;
        float m = -1e30f;
        for (int j=lane; j<NTOK; j+=32) m = fmaxf(m, Sr[j]);
        #pragma unroll
        for (int off=16;off;off>>=1) m = fmaxf(m, __shfl_xor_sync(0xffffffffu,m,off));
        float sum = 0.f;
        for (int j=lane; j<NTOK; j+=32){ float e = expf(Sr[j]-m); Sr[j]=e; sum+=e; }
        #pragma unroll
        for (int off=16;off;off>>=1) sum += __shfl_xor_sync(0xffffffffu,sum,off);
        float inv = 1.f/sum;
        for (int j=lane; j<NTOK; j+=32) Ph[i*PHS + j] = __float2half(Sr[j]*inv);
        for (int j=NTOK+lane; j<80; j+=32) Ph[i*PHS + j] = __float2half(0.f);
    }
    __syncthreads();

    // O = P @ V : 20 units of m16 x n16 (d), K=80
    for (int u = wid; u < 20; u += 8){
        int m0 = (u/4)*16, n0 = (u%4)*16;
        float acc[2][4];
        #pragma unroll
        for (int jj=0;jj<2;jj++)
            #pragma unroll
            for (int r=0;r<4;r++) acc[jj][r]=0.f;
        #pragma unroll
        for (int kt=0;kt<5;kt++){
            uint32_t a[4], bf[4];
            int ar = m0 + (lane&7) + ((lane>>3)&1)*8;
            int ak = kt*16 + (lane>>4)*8;
            ldsm4(a, ph_a + ar*(PHS*2) + ak*2);
            int bn_ = n0 + ((lane>>4)<<3) + (lane&7);
            int bk = kt*16 + ((lane>>3)&1)*8;
            ldsm4(bf, vt_a + bn_*(VTS*2) + bk*2);
            mma16816(acc[0], a, bf[0], bf[1]);
            mma16816(acc[1], a, bf[2], bf[3]);
        }
        #pragma unroll
        for (int jj=0;jj<2;jj++){
            int d = n0 + jj*8 + fc;
            int i0 = m0 + fr;
            if (i0 < NTOK){
                __half* op = o + (size_t)(b*NTOK + i0)*CDIM + hh*DHEAD + d;
                *(__half2*)op = __floats2half2_rn(acc[jj][0], acc[jj][1]);
            }
            if (i0+8 < NTOK){
                __half* op = o + (size_t)(b*NTOK + i0+8)*CDIM + hh*DHEAD + d;
                *(__half2*)op = __floats2half2_rn(acc[jj][2], acc[jj][3]);
            }
        }
    }
}

// ---------------- weight transpose: fp32 in[K][N] -> fp16 out[Npad][K] --------------
__global__ void transpose_pad_h(const float* __restrict__ in, __half* __restrict__ out,
                                int K, int N, int Npad)
{
    __shared__ float t[32][33];
    int kb = blockIdx.y*32, nb = blockIdx.x*32;
    #pragma unroll
    for (int i=0;i<4;i++){
        int k = kb + threadIdx.y + i*8, n = nb + threadIdx.x;
        t[threadIdx.y+i*8][threadIdx.x] = (k<K && n<N) ? in[(size_t)k*N + n] : 0.f;
    }
    __syncthreads();
    #pragma unroll
    for (int i=0;i<4;i++){
        int n = nb + threadIdx.y + i*8, k = kb + threadIdx.x;
        if (n<Npad && k<K) out[(size_t)n*K + k] = __float2half(t[threadIdx.x][threadIdx.y+i*8]);
    }
}

// ---------------- host ----------------
static inline void tlaunch(const float* in, __half* out, int K, int N, int Npad,
                           cudaStream_t st){
    transpose_pad_h<<<dim3((Npad+31)/32,(K+31)/32), dim3(32,8), 0, st>>>(in, out, K, N, Npad);
}

extern "C" void kernel_launch(void* const* d_in, const int* in_sizes, int n_in,
                              void* d_out, int out_size)
{
    (void)in_sizes; (void)n_in; (void)out_size;
    const float* ln1_g  = (const float*)d_in[1];
    const float* ln1_b  = (const float*)d_in[2];
    const float* qkv_w  = (const float*)d_in[3];
    const float* proj_w = (const float*)d_in[4];
    const float* qn_g   = (const float*)d_in[5];
    const float* qn_b   = (const float*)d_in[6];
    const float* kn_g   = (const float*)d_in[7];
    const float* kn_b   = (const float*)d_in[8];
    const float* sg_w1  = (const float*)d_in[9];
    const float* sg1g   = (const float*)d_in[10];
    const float* sg1b   = (const float*)d_in[11];
    const float* sg_w2  = (const float*)d_in[12];
    const float* sg2g   = (const float*)d_in[13];
    const float* sg2b   = (const float*)d_in[14];
    const float* bw     = (const float*)d_in[15];
    const float* ln2_g  = (const float*)d_in[16];
    const float* ln2_b  = (const float*)d_in[17];
    const float* gate_w = (const float*)d_in[18];
    const float* value_w= (const float*)d_in[19];
    const float* out_w  = (const float*)d_in[20];

    float* X = (float*)d_out;

    void *ph,*pqkv,*po,*pgated,*pbias,*psg1,*psg1h,*psg2,*psg2h;
    void *ptqkv,*ptproj,*ptgate,*ptval,*ptout,*ptsg1,*ptsg2,*ptbw;
    cudaGetSymbolAddress(&ph,g_h); cudaGetSymbolAddress(&pqkv,g_qkvh);
    cudaGetSymbolAddress(&po,g_o); cudaGetSymbolAddress(&pgated,g_gated);
    cudaGetSymbolAddress(&pbias,g_bias);
    cudaGetSymbolAddress(&psg1,g_sg1); cudaGetSymbolAddress(&psg1h,g_sg1h);
    cudaGetSymbolAddress(&psg2,g_sg2); cudaGetSymbolAddress(&psg2h,g_sg2h);
    cudaGetSymbolAddress(&ptqkv,g_tqkv); cudaGetSymbolAddress(&ptproj,g_tproj);
    cudaGetSymbolAddress(&ptgate,g_tgate); cudaGetSymbolAddress(&ptval,g_tval);
    cudaGetSymbolAddress(&ptout,g_tout); cudaGetSymbolAddress(&ptsg1,g_tsg1);
    cudaGetSymbolAddress(&ptsg2,g_tsg2); cudaGetSymbolAddress(&ptbw,g_tbw);
    __half* h=(__half*)ph; __half* qkvh=(__half*)pqkv; __half* o=(__half*)po;
    __half* gated=(__half*)pgated; float* bias=(float*)pbias;
    float* sg1=(float*)psg1; __half* sg1h=(__half*)psg1h;
    float* sg2=(float*)psg2; __half* sg2h=(__half*)psg2h;

    auto buf = [](void* base, int p, size_t n)->__half*{ return (__half*)base + (size_t)p*n; };

    static cudaStream_t s_sg = 0;
    static cudaEvent_t e_h[NUM_LAYERS], e_b[NUM_LAYERS], e_t[NUM_LAYERS+1];
    if (!s_sg){
        cudaStreamCreateWithFlags(&s_sg, cudaStreamNonBlocking);
        for (int l=0;l<NUM_LAYERS;l++){
            cudaEventCreateWithFlags(&e_h[l], cudaEventDisableTiming);
            cudaEventCreateWithFlags(&e_b[l], cudaEventDisableTiming);
            cudaEventCreateWithFlags(&e_t[l+1], cudaEventDisableTiming);
        }
    }

    const int attn_smem = 1024 + 11520 + 11520 + 11264 + 26880 + 14080;  // 76288
    cudaFuncSetAttribute(attn_kernel, cudaFuncAttributeMaxDynamicSharedMemorySize, attn_smem);
    const int g_smem = 2*NSTAGE*ASTG;
    const int d_smem = NSTAGE*ASTG + 2*NSTAGE*64*SROW;
    cudaFuncSetAttribute(gemm_h<0,false,false>, cudaFuncAttributeMaxDynamicSharedMemorySize, g_smem);
    cudaFuncSetAttribute(gemm_h<1,false,false>, cudaFuncAttributeMaxDynamicSharedMemorySize, g_smem);
    cudaFuncSetAttribute(gemm_h<0,true,false>,  cudaFuncAttributeMaxDynamicSharedMemorySize, g_smem);
    cudaFuncSetAttribute(gemm_h<0,false,true>,  cudaFuncAttributeMaxDynamicSharedMemorySize, g_smem);
    cudaFuncSetAttribute(gemm_dual_h,           cudaFuncAttributeMaxDynamicSharedMemorySize, d_smem);

    cudaMemcpyAsync(X, d_in[0], sizeof(float)*(size_t)ROWS*CDIM, cudaMemcpyDeviceToDevice);

    // layer-0 transposes on main stream
    {
        tlaunch(qkv_w,   buf(ptqkv,0,(size_t)C3*CDIM),  CDIM, C3,   C3,   0);
        tlaunch(proj_w,  buf(ptproj,0,(size_t)CDIM*CDIM),CDIM, CDIM, CDIM, 0);
        tlaunch(gate_w,  buf(ptgate,0,(size_t)C4*CDIM), CDIM, C4,   C4,   0);
        tlaunch(value_w, buf(ptval,0,(size_t)C4*CDIM),  CDIM, C4,   C4,   0);
        tlaunch(out_w,   buf(ptout,0,(size_t)CDIM*C4),  C4,   CDIM, CDIM, 0);
        tlaunch(sg_w1,   buf(ptsg1,0,(size_t)512*CDIM), CDIM, 512,  512,  0);
        tlaunch(sg_w2,   buf(ptsg2,0,(size_t)3072*512), 512,  3072, 3072, 0);
        tlaunch(bw,      buf(ptbw,0,(size_t)BIASNP*LATD),LATD, BIASN, BIASNP, 0);
    }

    for (int l=0; l<NUM_LAYERS; l++){
        const int p = l & 1;
        __half* tqkv = buf(ptqkv,p,(size_t)C3*CDIM);
        __half* tproj= buf(ptproj,p,(size_t)CDIM*CDIM);
        __half* tgate= buf(ptgate,p,(size_t)C4*CDIM);
        __half* tval = buf(ptval,p,(size_t)C4*CDIM);
        __half* tout = buf(ptout,p,(size_t)CDIM*C4);
        __half* tsg1 = buf(ptsg1,p,(size_t)512*CDIM);
        __half* tsg2 = buf(ptsg2,p,(size_t)3072*512);
        __half* tbw  = buf(ptbw,p,(size_t)BIASNP*LATD);

        // h = LN1(x)
        ln_h_kernel<<<ROWS,256>>>(X, h, ln1_g+(size_t)l*CDIM, ln1_b+(size_t)l*CDIM, CDIM, 0);
        cudaEventRecord(e_h[l], 0);
        cudaStreamWaitEvent(s_sg, e_h[l], 0);

        // side stream: structure-gate bias chain
        gemm_h<0,false,false><<<dim3(4,4), 256, g_smem, s_sg>>>(
            h, tsg1, sg1, 512, 512, CDIM, NTOK*CDIM, 512);
        ln_h_kernel<<<512,256,0,s_sg>>>(sg1, sg1h, sg1g+(size_t)l*512, sg1b+(size_t)l*512, 512, 1);
        gemm_h<0,false,false><<<dim3(24,4), 256, g_smem, s_sg>>>(
            sg1h, tsg2, sg2, 512, 3072, 512, 512, 3072);
        ln_h_kernel<<<512,256,0,s_sg>>>(sg2, sg2h, sg2g+(size_t)l*3072, sg2b+(size_t)l*3072, 3072, 0);
        gemm_h<0,true,false><<<dim3(BIASNP/128, BHD/128), 256, g_smem, s_sg>>>(
            sg2h, tbw, bias, BHD, BIASN, LATD, LATD, BIASN);
        cudaEventRecord(e_b[l], s_sg);

        // side stream: prefetch next-layer transposes
        if (l+1 < NUM_LAYERS){
            const int q = (l+1)&1;
            tlaunch(qkv_w  + (size_t)(l+1)*CDIM*C3,   buf(ptqkv,q,(size_t)C3*CDIM),  CDIM, C3,   C3,   s_sg);
            tlaunch(proj_w + (size_t)(l+1)*CDIM*CDIM, buf(ptproj,q,(size_t)CDIM*CDIM),CDIM, CDIM, CDIM, s_sg);
            tlaunch(gate_w + (size_t)(l+1)*CDIM*C4,   buf(ptgate,q,(size_t)C4*CDIM), CDIM, C4,   C4,   s_sg);
            tlaunch(value_w+ (size_t)(l+1)*CDIM*C4,   buf(ptval,q,(size_t)C4*CDIM),  CDIM, C4,   C4,   s_sg);
            tlaunch(out_w  + (size_t)(l+1)*C4*CDIM,   buf(ptout,q,(size_t)CDIM*C4),  C4,   CDIM, CDIM, s_sg);
            tlaunch(sg_w1  + (size_t)(l+1)*CDIM*512,  buf(ptsg1,q,(size_t)512*CDIM), CDIM, 512,  512,  s_sg);
            tlaunch(sg_w2  + (size_t)(l+1)*512*3072,  buf(ptsg2,q,(size_t)3072*512), 512,  3072, 3072, s_sg);
            tlaunch(bw     + (size_t)(l+1)*LATD*BIASN,buf(ptbw,q,(size_t)BIASNP*LATD),LATD, BIASN, BIASNP, s_sg);
            cudaEventRecord(e_t[l+1], s_sg);
        }

        // main stream: qkv GEMM (fp16 out), overlaps side chain
        gemm_h<0,false,true><<<dim3(C3/128, ROWS/128), 256, g_smem>>>(
            h, tqkv, qkvh, ROWS, C3, CDIM, CDIM, C3);

        // join side chain, then tensorized attention
        cudaStreamWaitEvent(0, e_b[l], 0);
        attn_kernel<<<BHD, 256, attn_smem>>>(qkvh, bias, o,
            qn_g+(size_t)l*DHEAD, qn_b+(size_t)l*DHEAD,
            kn_g+(size_t)l*DHEAD, kn_b+(size_t)l*DHEAD);
        // x += o @ proj_w
        gemm_h<1,false,false><<<dim3(CDIM/128, ROWS/128), 256, g_smem>>>(
            o, tproj, X, ROWS, CDIM, CDIM, CDIM, CDIM);
        // h2 = LN2(x)
        ln_h_kernel<<<ROWS,256>>>(X, h, ln2_g+(size_t)l*CDIM, ln2_b+(size_t)l*CDIM, CDIM, 0);
        // gated = (h2@gate_w) * silu(h2@value_w)
        gemm_dual_h<<<dim3(C4/64, ROWS/128), 256, d_smem>>>(
            h, tgate, tval, gated, ROWS, C4, CDIM, CDIM, C4);
        // x += gated @ out_w
        gemm_h<1,false,false><<<dim3(CDIM/128, ROWS/128), 256, g_smem>>>(
            gated, tout, X, ROWS, CDIM, C4, C4, CDIM);

        if (l+1 < NUM_LAYERS) cudaStreamWaitEvent(0, e_t[l+1], 0);
    }
}